// round 8
// baseline (speedup 1.0000x reference)
#include <cuda_runtime.h>
#include <cuda_fp16.h>
#include <math.h>
#include <stdint.h>

// Problem dims
#define Bn 8
#define Tn 1024
#define Dn 512
#define Hn 1024
#define En 8
#define Kn 2
#define Nn (Bn * Tn)          // 8192 tokens
#define LOG_2PI 1.8378770664093453f

// ---------------- scratch (static __device__ globals) ----------------------
__device__ __half g_hh[(size_t)Nn * Kn * Hn];          // gelu(h) fp16, [slot][H]
__device__ __half g_xh[(size_t)Nn * Dn];               // x cast to fp16
__device__ float  g_gate[Nn * Kn];
__device__ int    g_counts[En];
__device__ int    g_list[En][Nn];
__device__ float2 g_tab[Bn * En * Dn];                 // (isig2, mu*isig2)
__device__ float  g_C[Bn * En];                        // per-(b,e) constant
__device__ __half g_w1h[(size_t)En * Hn * Dn];         // W1^T [E][H][D] hi
__device__ __half g_w1l[(size_t)En * Hn * Dn];         // lo
__device__ __half g_w2h[(size_t)En * Dn * Hn];         // W2^T [E][D][H] hi
__device__ __half g_w2l[(size_t)En * Dn * Hn];

// ---------------- helpers ---------------------------------------------------
__device__ __forceinline__ uint32_t smem_u32(const void* p) {
    uint32_t a;
    asm("{ .reg .u64 t; cvta.to.shared.u64 t, %1; cvt.u32.u64 %0, t; }" : "=r"(a) : "l"(p));
    return a;
}
__device__ __forceinline__ void ldsm4(uint32_t* r, uint32_t addr) {
    asm volatile("ldmatrix.sync.aligned.m8n8.x4.shared.b16 {%0,%1,%2,%3}, [%4];"
        : "=r"(r[0]), "=r"(r[1]), "=r"(r[2]), "=r"(r[3]) : "r"(addr));
}
__device__ __forceinline__ void mma16816(float* c, const uint32_t* a, const uint32_t* b) {
    asm volatile("mma.sync.aligned.m16n8k16.row.col.f32.f16.f16.f32 "
        "{%0,%1,%2,%3}, {%4,%5,%6,%7}, {%8,%9}, {%0,%1,%2,%3};"
        : "+f"(c[0]), "+f"(c[1]), "+f"(c[2]), "+f"(c[3])
        : "r"(a[0]), "r"(a[1]), "r"(a[2]), "r"(a[3]), "r"(b[0]), "r"(b[1]));
}
#define CPA16(dst, src) asm volatile("cp.async.cg.shared.global [%0], [%1], 16;" :: "r"(dst), "l"(src) : "memory")
#define CPC()  asm volatile("cp.async.commit_group;" ::: "memory")
#define CPW2() asm volatile("cp.async.wait_group 2;" ::: "memory")
#define CPW1() asm volatile("cp.async.wait_group 1;" ::: "memory")
#define CPW0() asm volatile("cp.async.wait_group 0;" ::: "memory")

// ---------------- kernel: precompute gate table + zero counts --------------
__global__ void precompute_kernel(const float* __restrict__ log_sigmas,
                                  const float* __restrict__ mus) {
    int be = blockIdx.x;              // b*En + e
    int tid = threadIdx.x;            // 256
    if (be == 0 && tid < En) g_counts[tid] = 0;
    __shared__ float red[256];
    float s = 0.0f;
    for (int d = tid; d < Dn; d += 256) {
        float ls = log_sigmas[be * Dn + d];
        float mu = mus[be * Dn + d];
        float s2 = __expf(-2.0f * ls);
        g_tab[be * Dn + d] = make_float2(s2, mu * s2);
        s += -0.5f * mu * mu * s2 - ls;
    }
    red[tid] = s;
    __syncthreads();
    for (int o = 128; o > 0; o >>= 1) {
        if (tid < o) red[tid] += red[tid + o];
        __syncthreads();
    }
    if (tid == 0) g_C[be] = red[0] - 0.5f * LOG_2PI * (float)Dn;
}

// ---------------- kernel: transpose + fp16 hi/lo split ---------------------
// src [E][R][C] fp32 -> dst [E][C][R] half. Tiles 64R x 32C, coalesced half2 out.
__global__ __launch_bounds__(256) void transpose_split_kernel(
        const float* __restrict__ src,
        __half* __restrict__ dhi,
        __half* __restrict__ dlo,
        int R, int C) {
    __shared__ float t[64][33];
    int e = blockIdx.z;
    int c0 = blockIdx.x * 32, r0 = blockIdx.y * 64;
    int tid = threadIdx.x;
    const float* s = src + (size_t)e * R * C;
#pragma unroll
    for (int p = 0; p < 8; p++) {
        int i = tid + p * 256;
        int r = i >> 5, c = i & 31;
        t[r][c] = s[(size_t)(r0 + r) * C + c0 + c];
    }
    __syncthreads();
    size_t obase = (size_t)e * C * R + r0;
#pragma unroll
    for (int p = 0; p < 4; p++) {
        int i = tid + p * 256;
        int oc = i >> 5, j = i & 31;
        float v0 = t[2 * j][oc];
        float v1 = t[2 * j + 1][oc];
        __half h0 = __float2half_rn(v0);
        __half h1 = __float2half_rn(v1);
        __half l0 = __float2half_rn(v0 - __half2float(h0));
        __half l1 = __float2half_rn(v1 - __half2float(h1));
        uint32_t ph = (uint32_t)*(uint16_t*)&h0 | ((uint32_t)*(uint16_t*)&h1 << 16);
        uint32_t pl = (uint32_t)*(uint16_t*)&l0 | ((uint32_t)*(uint16_t*)&l1 << 16);
        size_t o = obase + (size_t)(c0 + oc) * R + 2 * j;
        *(uint32_t*)(dhi + o) = ph;
        *(uint32_t*)(dlo + o) = pl;
    }
}

// ---------------- kernel: gating + fused x->fp16 cast ----------------------
// 64 tokens per CTA (each of 8 warps handles 8 tokens sequentially).
__global__ __launch_bounds__(256) void gate_kernel(const float* __restrict__ x,
                                                   __half* __restrict__ xh,
                                                   float* __restrict__ out_lp,
                                                   float* __restrict__ out_ti,
                                                   int has_lp, int has_ti) {
    __shared__ float2 stab[En * Dn];   // 32 KB
    int tid = threadIdx.x;
    int warp = tid >> 5, lane = tid & 31;
    int b = blockIdx.x >> 4;           // 16 CTAs per batch (1024 tokens / 64)

    for (int i = tid; i < En * Dn; i += 256) stab[i] = g_tab[b * En * Dn + i];
    __syncthreads();

    for (int tt = 0; tt < 8; tt++) {
        int t = blockIdx.x * 64 + warp * 8 + tt;

        float xr[16], xr2[16];
#pragma unroll
        for (int i = 0; i < 16; i++) {
            xr[i] = x[t * Dn + lane + 32 * i];
            xr2[i] = xr[i] * xr[i];
        }
#pragma unroll
        for (int i = 0; i < 16; i++)
            xh[t * Dn + lane + 32 * i] = __float2half_rn(xr[i]);

        float lp[En];
#pragma unroll
        for (int e = 0; e < En; e++) {
            const float2* tb = stab + e * Dn;
            float a1 = 0.0f, a2 = 0.0f;
#pragma unroll
            for (int i = 0; i < 16; i++) {
                float2 p = tb[lane + 32 * i];
                a1 = fmaf(xr2[i], p.x, a1);
                a2 = fmaf(xr[i], p.y, a2);
            }
            float sacc = a2 - 0.5f * a1;
#pragma unroll
            for (int o = 16; o > 0; o >>= 1) sacc += __shfl_xor_sync(0xffffffffu, sacc, o);
            lp[e] = sacc + g_C[b * En + e];
        }

        if (lane == 0) {
            int e0 = 0;
#pragma unroll
            for (int e = 1; e < En; e++) if (lp[e] > lp[e0]) e0 = e;
            int e1 = -1;
#pragma unroll
            for (int e = 0; e < En; e++) {
                if (e == e0) continue;
                if (e1 < 0 || lp[e] > lp[e1]) e1 = e;
            }
            float p1 = __expf(lp[e1] - lp[e0]);
            float inv = 1.0f / (1.0f + p1);
            g_gate[t * 2 + 0] = inv;
            g_gate[t * 2 + 1] = p1 * inv;
            int p = atomicAdd(&g_counts[e0], 1);
            g_list[e0][p] = (t << 1) | 0;
            p = atomicAdd(&g_counts[e1], 1);
            g_list[e1][p] = (t << 1) | 1;
            if (has_lp) {
#pragma unroll
                for (int e = 0; e < En; e++) out_lp[t * En + e] = lp[e];
            }
            if (has_ti) {
                out_ti[t * 2 + 0] = (float)e0;
                out_ti[t * 2 + 1] = (float)e1;
            }
        }
    }
}

// ---------------- warp-MMA grouped GEMM, 3-stage cp.async pipeline ---------
// CTA 128x128, 8 warps (warp tile 32x64), K-step 32.
// A fp16 single, B fp16 hi+lo: out = Ah*Bh + Ah*Bl.
// MODE 0: h = gelu(xh @ W1T + b1) -> g_hh fp16. K=512, N=1024, A row = en>>1.
// MODE 1: y[t] += gate*(g_hh @ W2T + b2) via RED. K=1024, N=512, A row = en.
#define ROWB 80
#define STG_BYTES (3 * 128 * ROWB)    // A + Bh + Bl per stage = 30720
#define NSTG 3
template <int MODE>
__global__ __launch_bounds__(256) void gemm_mma(const __half* __restrict__ Aglob,
                                                const __half* __restrict__ Bhg,
                                                const __half* __restrict__ Blg,
                                                const float* __restrict__ bias,
                                                float* __restrict__ outf,
                                                __half* __restrict__ outh) {
    constexpr int Ktot = MODE ? Hn : Dn;
    constexpr int Ntot = MODE ? Dn : Hn;
    constexpr int NCH = Ktot / 32;

    int e = blockIdx.z;
    int cnt = g_counts[e];
    int row0 = blockIdx.y * 128;
    if (row0 >= cnt) return;
    int n0 = blockIdx.x * 128;

    extern __shared__ char sdyn[];
    __shared__ int ent[128];
    __shared__ int rowIdx[128];
    __shared__ float gw[128];

    int tid = threadIdx.x, lane = tid & 31, wid = tid >> 5;
    int warp_m = wid & 3, warp_n = wid >> 2;

    if (tid < 128) {
        int en = (row0 + tid < cnt) ? g_list[e][row0 + tid] : -1;
        ent[tid] = en;
        gw[tid] = (en >= 0) ? g_gate[en] : 0.0f;
        int safe = g_list[e][row0];
        int use = (en >= 0) ? en : safe;
        rowIdx[tid] = MODE ? use : (use >> 1);
    }
    __syncthreads();

    const __half* Bhe = Bhg + (size_t)e * Ntot * Ktot + (size_t)n0 * Ktot;
    const __half* Ble = Blg + (size_t)e * Ntot * Ktot + (size_t)n0 * Ktot;
    uint32_t sbase = smem_u32(sdyn);

    float c[2][8][4];
#pragma unroll
    for (int i = 0; i < 2; i++)
#pragma unroll
        for (int j = 0; j < 8; j++)
#pragma unroll
            for (int q = 0; q < 4; q++) c[i][j][q] = 0.0f;

    uint32_t a_row = (uint32_t)(lane & 15);
    uint32_t a_kh  = (uint32_t)((lane >> 4) << 3);
    uint32_t b_row = (uint32_t)((lane & 7) + ((lane >> 4) << 3));
    uint32_t b_kh  = (uint32_t)(lane & 8);

    auto prefetch = [&](int k0, int s) {
        uint32_t base = sbase + s * STG_BYTES;
#pragma unroll
        for (int j = 0; j < 2; j++) {
            int i = tid + 256 * j;
            int m = i >> 2, cc = i & 3;
            const __half* src = Aglob + (size_t)rowIdx[m] * Ktot + k0 + cc * 8;
            CPA16(base + m * ROWB + cc * 16, src);
        }
#pragma unroll
        for (int j = 0; j < 2; j++) {
            int i = tid + 256 * j;
            int n = i >> 2, cc = i & 3;
            CPA16(base + 128 * ROWB + n * ROWB + cc * 16, Bhe + (size_t)n * Ktot + k0 + cc * 8);
            CPA16(base + 2 * 128 * ROWB + n * ROWB + cc * 16, Ble + (size_t)n * Ktot + k0 + cc * 8);
        }
    };

    prefetch(0, 0);
    CPC();
    prefetch(32, 1);
    CPC();

    for (int cc = 0; cc < NCH; cc++) {
        int s = cc % NSTG;
        if (cc + 2 < NCH) {
            prefetch((cc + 2) * 32, (cc + 2) % NSTG);
            CPC();
            CPW2();
        } else if (cc + 1 < NCH) {
            CPW1();
        } else {
            CPW0();
        }
        __syncthreads();

        uint32_t baseA = sbase + s * STG_BYTES;
        uint32_t baseBh = baseA + 128 * ROWB;
        uint32_t baseBl = baseBh + 128 * ROWB;
#pragma unroll
        for (int kk = 0; kk < 2; kk++) {
            uint32_t ka = (uint32_t)(kk * 32) + a_kh * 2;
            uint32_t ah[2][4];
#pragma unroll
            for (int mt = 0; mt < 2; mt++) {
                uint32_t ro = (uint32_t)(warp_m * 32 + mt * 16) + a_row;
                ldsm4(ah[mt], baseA + ro * ROWB + ka);
            }
            uint32_t kb = (uint32_t)(kk * 32) + b_kh * 2;
            uint32_t bh[8][2], bl[8][2];
#pragma unroll
            for (int p = 0; p < 4; p++) {
                uint32_t ro = (uint32_t)(warp_n * 64 + p * 16) + b_row;
                uint32_t r4[4];
                ldsm4(r4, baseBh + ro * ROWB + kb);
                bh[2 * p][0] = r4[0]; bh[2 * p][1] = r4[1];
                bh[2 * p + 1][0] = r4[2]; bh[2 * p + 1][1] = r4[3];
                ldsm4(r4, baseBl + ro * ROWB + kb);
                bl[2 * p][0] = r4[0]; bl[2 * p][1] = r4[1];
                bl[2 * p + 1][0] = r4[2]; bl[2 * p + 1][1] = r4[3];
            }
#pragma unroll
            for (int mt = 0; mt < 2; mt++)
#pragma unroll
                for (int nt = 0; nt < 8; nt++) {
                    mma16816(c[mt][nt], ah[mt], bh[nt]);
                    mma16816(c[mt][nt], ah[mt], bl[nt]);
                }
        }
        __syncthreads();
    }

    // ---- epilogue ----
#pragma unroll
    for (int mt = 0; mt < 2; mt++) {
#pragma unroll
        for (int nt = 0; nt < 8; nt++) {
            int col = n0 + warp_n * 64 + nt * 8 + (lane & 3) * 2;
#pragma unroll
            for (int half = 0; half < 2; half++) {
                int m = warp_m * 32 + mt * 16 + (lane >> 2) + half * 8;
                int en = ent[m];
                if (en < 0) continue;
                float v0 = c[mt][nt][half * 2 + 0] + bias[e * Ntot + col];
                float v1 = c[mt][nt][half * 2 + 1] + bias[e * Ntot + col + 1];
                if (MODE == 0) {
                    float ga = 0.5f * v0 * (1.0f + erff(v0 * 0.7071067811865476f));
                    float gb = 0.5f * v1 * (1.0f + erff(v1 * 0.7071067811865476f));
                    __half2 h2 = __floats2half2_rn(ga, gb);
                    *(uint32_t*)(outh + (size_t)en * Hn + col) = *(uint32_t*)&h2;
                } else {
                    float g = gw[m];
                    int t = en >> 1;
                    atomicAdd(outf + (size_t)t * Dn + col, v0 * g);
                    atomicAdd(outf + (size_t)t * Dn + col + 1, v1 * g);
                }
            }
        }
    }
}

// ---------------- launch ----------------------------------------------------
extern "C" void kernel_launch(void* const* d_in, const int* in_sizes, int n_in,
                              void* d_out, int out_size) {
    const float* x   = (const float*)d_in[0];
    const float* mus = (const float*)d_in[1];
    const float* ls  = (const float*)d_in[2];
    const float* W1  = (const float*)d_in[3];
    const float* b1  = (const float*)d_in[4];
    const float* W2  = (const float*)d_in[5];
    const float* b2  = (const float*)d_in[6];
    float* out = (float*)d_out;

    const int Ny  = Nn * Dn;
    const int Nlp = Nn * En;
    const int Nti = Nn * Kn;
    int has_lp = (out_size >= Ny + Nlp) ? 1 : 0;
    int has_ti = (out_size >= Ny + Nlp + Nti) ? 1 : 0;
    float* out_lp = out + Ny;
    float* out_ti = out + Ny + Nlp;

    cudaFuncSetAttribute(gemm_mma<0>, cudaFuncAttributeMaxDynamicSharedMemorySize, NSTG * STG_BYTES);
    cudaFuncSetAttribute(gemm_mma<1>, cudaFuncAttributeMaxDynamicSharedMemorySize, NSTG * STG_BYTES);

    // zero the y region (gemm2 accumulates into it via RED)
    cudaMemsetAsync(out, 0, (size_t)Ny * sizeof(float));

    precompute_kernel<<<Bn * En, 256>>>(ls, mus);

    __half *w1h, *w1l, *w2h, *w2l, *hh, *xh;
    cudaGetSymbolAddress((void**)&w1h, g_w1h);
    cudaGetSymbolAddress((void**)&w1l, g_w1l);
    cudaGetSymbolAddress((void**)&w2h, g_w2h);
    cudaGetSymbolAddress((void**)&w2l, g_w2l);
    cudaGetSymbolAddress((void**)&hh, g_hh);
    cudaGetSymbolAddress((void**)&xh, g_xh);

    // W1 [E][D][H] -> [E][H][D] split: R=Dn, C=Hn
    dim3 t1(Hn / 32, Dn / 64, En);
    transpose_split_kernel<<<t1, 256>>>(W1, w1h, w1l, Dn, Hn);
    // W2 [E][H][D] -> [E][D][H] split: R=Hn, C=Dn
    dim3 t2(Dn / 32, Hn / 64, En);
    transpose_split_kernel<<<t2, 256>>>(W2, w2h, w2l, Hn, Dn);

    gate_kernel<<<Nn / 64, 256>>>(x, xh, out_lp, out_ti, has_lp, has_ti);

    dim3 g1(Hn / 128, Nn / 128, En);
    gemm_mma<0><<<g1, 256, NSTG * STG_BYTES>>>(xh, w1h, w1l, b1, nullptr, hh);

    dim3 g2(Dn / 128, Nn / 128, En);
    gemm_mma<1><<<g2, 256, NSTG * STG_BYTES>>>(hh, w2h, w2l, b2, out, nullptr);

    (void)in_sizes; (void)n_in;
}

// round 9
// speedup vs baseline: 1.4482x; 1.4482x over previous
#include <cuda_runtime.h>
#include <cuda_fp16.h>
#include <math.h>
#include <stdint.h>

// Problem dims
#define Bn 8
#define Tn 1024
#define Dn 512
#define Hn 1024
#define En 8
#define Kn 2
#define Nn (Bn * Tn)          // 8192 tokens
#define LOG_2PI 1.8378770664093453f

// ---------------- scratch (static __device__ globals) ----------------------
__device__ __half g_hh[(size_t)Nn * Kn * Hn];          // gelu(h) fp16, [slot][H]
__device__ __half g_xh[(size_t)Nn * Dn];               // x cast to fp16
__device__ float  g_gate[Nn * Kn];
__device__ int    g_counts[En];
__device__ int    g_list[En][Nn];
__device__ float2 g_tab[Bn * En * Dn];                 // (isig2, mu*isig2)
__device__ float  g_C[Bn * En];                        // per-(b,e) constant
__device__ __half g_w1[(size_t)En * Hn * Dn];          // W1^T [E][H][D] fp16
__device__ __half g_w2[(size_t)En * Dn * Hn];          // W2^T [E][D][H] fp16

// ---------------- helpers ---------------------------------------------------
__device__ __forceinline__ uint32_t smem_u32(const void* p) {
    uint32_t a;
    asm("{ .reg .u64 t; cvta.to.shared.u64 t, %1; cvt.u32.u64 %0, t; }" : "=r"(a) : "l"(p));
    return a;
}
__device__ __forceinline__ void ldsm4(uint32_t* r, uint32_t addr) {
    asm volatile("ldmatrix.sync.aligned.m8n8.x4.shared.b16 {%0,%1,%2,%3}, [%4];"
        : "=r"(r[0]), "=r"(r[1]), "=r"(r[2]), "=r"(r[3]) : "r"(addr));
}
__device__ __forceinline__ void mma16816(float* c, const uint32_t* a, const uint32_t* b) {
    asm volatile("mma.sync.aligned.m16n8k16.row.col.f32.f16.f16.f32 "
        "{%0,%1,%2,%3}, {%4,%5,%6,%7}, {%8,%9}, {%0,%1,%2,%3};"
        : "+f"(c[0]), "+f"(c[1]), "+f"(c[2]), "+f"(c[3])
        : "r"(a[0]), "r"(a[1]), "r"(a[2]), "r"(a[3]), "r"(b[0]), "r"(b[1]));
}
#define CPA16(dst, src) asm volatile("cp.async.cg.shared.global [%0], [%1], 16;" :: "r"(dst), "l"(src) : "memory")
#define CPC()  asm volatile("cp.async.commit_group;" ::: "memory")
#define CPW2() asm volatile("cp.async.wait_group 2;" ::: "memory")
#define CPW1() asm volatile("cp.async.wait_group 1;" ::: "memory")
#define CPW0() asm volatile("cp.async.wait_group 0;" ::: "memory")

// ---------------- kernel: precompute gate table + zero counts --------------
__global__ void precompute_kernel(const float* __restrict__ log_sigmas,
                                  const float* __restrict__ mus) {
    int be = blockIdx.x;              // b*En + e
    int tid = threadIdx.x;            // 256
    if (be == 0 && tid < En) g_counts[tid] = 0;
    __shared__ float red[256];
    float s = 0.0f;
    for (int d = tid; d < Dn; d += 256) {
        float ls = log_sigmas[be * Dn + d];
        float mu = mus[be * Dn + d];
        float s2 = __expf(-2.0f * ls);
        g_tab[be * Dn + d] = make_float2(s2, mu * s2);
        s += -0.5f * mu * mu * s2 - ls;
    }
    red[tid] = s;
    __syncthreads();
    for (int o = 128; o > 0; o >>= 1) {
        if (tid < o) red[tid] += red[tid + o];
        __syncthreads();
    }
    if (tid == 0) g_C[be] = red[0] - 0.5f * LOG_2PI * (float)Dn;
}

// ---------------- kernel: transpose to fp16 ---------------------------------
// src [E][R][C] fp32 -> dst [E][C][R] half. Tiles 64R x 32C, coalesced half2 out.
__global__ __launch_bounds__(256) void transpose_kernel(
        const float* __restrict__ src,
        __half* __restrict__ dst,
        int R, int C) {
    __shared__ float t[64][33];
    int e = blockIdx.z;
    int c0 = blockIdx.x * 32, r0 = blockIdx.y * 64;
    int tid = threadIdx.x;
    const float* s = src + (size_t)e * R * C;
#pragma unroll
    for (int p = 0; p < 8; p++) {
        int i = tid + p * 256;
        int r = i >> 5, c = i & 31;
        t[r][c] = s[(size_t)(r0 + r) * C + c0 + c];
    }
    __syncthreads();
    size_t obase = (size_t)e * C * R + r0;
#pragma unroll
    for (int p = 0; p < 4; p++) {
        int i = tid + p * 256;
        int oc = i >> 5, j = i & 31;
        __half2 h2 = __floats2half2_rn(t[2 * j][oc], t[2 * j + 1][oc]);
        *(uint32_t*)(dst + obase + (size_t)(c0 + oc) * R + 2 * j) = *(uint32_t*)&h2;
    }
}

// ---------------- kernel: gating + fused x->fp16 cast ----------------------
// 32 tokens per CTA (each of 8 warps handles 4 tokens sequentially). grid=256.
__global__ __launch_bounds__(256) void gate_kernel(const float* __restrict__ x,
                                                   __half* __restrict__ xh,
                                                   float* __restrict__ out_lp,
                                                   float* __restrict__ out_ti,
                                                   int has_lp, int has_ti) {
    __shared__ float2 stab[En * Dn];   // 32 KB
    int tid = threadIdx.x;
    int warp = tid >> 5, lane = tid & 31;
    int b = blockIdx.x >> 5;           // 32 CTAs per batch (1024 tokens / 32)

    for (int i = tid; i < En * Dn; i += 256) stab[i] = g_tab[b * En * Dn + i];
    __syncthreads();

    for (int tt = 0; tt < 4; tt++) {
        int t = blockIdx.x * 32 + warp * 4 + tt;

        float xr[16], xr2[16];
#pragma unroll
        for (int i = 0; i < 16; i++) {
            xr[i] = x[t * Dn + lane + 32 * i];
            xr2[i] = xr[i] * xr[i];
        }
#pragma unroll
        for (int i = 0; i < 16; i++)
            xh[t * Dn + lane + 32 * i] = __float2half_rn(xr[i]);

        float lp[En];
#pragma unroll
        for (int e = 0; e < En; e++) {
            const float2* tb = stab + e * Dn;
            float a1 = 0.0f, a2 = 0.0f;
#pragma unroll
            for (int i = 0; i < 16; i++) {
                float2 p = tb[lane + 32 * i];
                a1 = fmaf(xr2[i], p.x, a1);
                a2 = fmaf(xr[i], p.y, a2);
            }
            float sacc = a2 - 0.5f * a1;
#pragma unroll
            for (int o = 16; o > 0; o >>= 1) sacc += __shfl_xor_sync(0xffffffffu, sacc, o);
            lp[e] = sacc + g_C[b * En + e];
        }

        if (lane == 0) {
            int e0 = 0;
#pragma unroll
            for (int e = 1; e < En; e++) if (lp[e] > lp[e0]) e0 = e;
            int e1 = -1;
#pragma unroll
            for (int e = 0; e < En; e++) {
                if (e == e0) continue;
                if (e1 < 0 || lp[e] > lp[e1]) e1 = e;
            }
            float p1 = __expf(lp[e1] - lp[e0]);
            float inv = 1.0f / (1.0f + p1);
            g_gate[t * 2 + 0] = inv;
            g_gate[t * 2 + 1] = p1 * inv;
            int p = atomicAdd(&g_counts[e0], 1);
            g_list[e0][p] = (t << 1) | 0;
            p = atomicAdd(&g_counts[e1], 1);
            g_list[e1][p] = (t << 1) | 1;
            if (has_lp) {
#pragma unroll
                for (int e = 0; e < En; e++) out_lp[t * En + e] = lp[e];
            }
            if (has_ti) {
                out_ti[t * 2 + 0] = (float)e0;
                out_ti[t * 2 + 1] = (float)e1;
            }
        }
    }
}

// ---------------- warp-MMA grouped GEMM, 3-stage cp.async pipeline ---------
// CTA 128x128, 8 warps (warp tile 32x64), K-step 32. Pure fp16 A and B.
// MODE 0: h = gelu(xh @ W1T + b1) -> g_hh fp16. K=512, N=1024, A row = en>>1.
// MODE 1: y[t] += gate*(g_hh @ W2T + b2) via RED. K=1024, N=512, A row = en.
#define ROWB 80
#define STG_BYTES (2 * 128 * ROWB)    // A + B per stage = 20480
#define NSTG 3
template <int MODE>
__global__ __launch_bounds__(256) void gemm_mma(const __half* __restrict__ Aglob,
                                                const __half* __restrict__ Bg,
                                                const float* __restrict__ bias,
                                                float* __restrict__ outf,
                                                __half* __restrict__ outh) {
    constexpr int Ktot = MODE ? Hn : Dn;
    constexpr int Ntot = MODE ? Dn : Hn;
    constexpr int NCH = Ktot / 32;

    int e = blockIdx.z;
    int cnt = g_counts[e];
    int row0 = blockIdx.y * 128;
    if (row0 >= cnt) return;
    int n0 = blockIdx.x * 128;

    extern __shared__ char sdyn[];
    __shared__ int ent[128];
    __shared__ int rowIdx[128];
    __shared__ float gw[128];

    int tid = threadIdx.x, lane = tid & 31, wid = tid >> 5;
    int warp_m = wid & 3, warp_n = wid >> 2;

    if (tid < 128) {
        int en = (row0 + tid < cnt) ? g_list[e][row0 + tid] : -1;
        ent[tid] = en;
        gw[tid] = (en >= 0) ? g_gate[en] : 0.0f;
        int safe = g_list[e][row0];
        int use = (en >= 0) ? en : safe;
        rowIdx[tid] = MODE ? use : (use >> 1);
    }
    __syncthreads();

    const __half* Be = Bg + (size_t)e * Ntot * Ktot + (size_t)n0 * Ktot;
    uint32_t sbase = smem_u32(sdyn);

    float c[2][8][4];
#pragma unroll
    for (int i = 0; i < 2; i++)
#pragma unroll
        for (int j = 0; j < 8; j++)
#pragma unroll
            for (int q = 0; q < 4; q++) c[i][j][q] = 0.0f;

    uint32_t a_row = (uint32_t)(lane & 15);
    uint32_t a_kh  = (uint32_t)((lane >> 4) << 3);
    uint32_t b_row = (uint32_t)((lane & 7) + ((lane >> 4) << 3));
    uint32_t b_kh  = (uint32_t)(lane & 8);

    auto prefetch = [&](int k0, int s) {
        uint32_t base = sbase + s * STG_BYTES;
#pragma unroll
        for (int j = 0; j < 2; j++) {
            int i = tid + 256 * j;
            int m = i >> 2, cc = i & 3;
            const __half* src = Aglob + (size_t)rowIdx[m] * Ktot + k0 + cc * 8;
            CPA16(base + m * ROWB + cc * 16, src);
        }
#pragma unroll
        for (int j = 0; j < 2; j++) {
            int i = tid + 256 * j;
            int n = i >> 2, cc = i & 3;
            CPA16(base + 128 * ROWB + n * ROWB + cc * 16, Be + (size_t)n * Ktot + k0 + cc * 8);
        }
    };

    prefetch(0, 0);
    CPC();
    prefetch(32, 1);
    CPC();

    for (int cc = 0; cc < NCH; cc++) {
        int s = cc % NSTG;
        if (cc + 2 < NCH) {
            prefetch((cc + 2) * 32, (cc + 2) % NSTG);
            CPC();
            CPW2();
        } else if (cc + 1 < NCH) {
            CPW1();
        } else {
            CPW0();
        }
        __syncthreads();

        uint32_t baseA = sbase + s * STG_BYTES;
        uint32_t baseB = baseA + 128 * ROWB;
#pragma unroll
        for (int kk = 0; kk < 2; kk++) {
            uint32_t ka = (uint32_t)(kk * 32) + a_kh * 2;
            uint32_t ah[2][4];
#pragma unroll
            for (int mt = 0; mt < 2; mt++) {
                uint32_t ro = (uint32_t)(warp_m * 32 + mt * 16) + a_row;
                ldsm4(ah[mt], baseA + ro * ROWB + ka);
            }
            uint32_t kb = (uint32_t)(kk * 32) + b_kh * 2;
            uint32_t bh[8][2];
#pragma unroll
            for (int p = 0; p < 4; p++) {
                uint32_t ro = (uint32_t)(warp_n * 64 + p * 16) + b_row;
                uint32_t r4[4];
                ldsm4(r4, baseB + ro * ROWB + kb);
                bh[2 * p][0] = r4[0]; bh[2 * p][1] = r4[1];
                bh[2 * p + 1][0] = r4[2]; bh[2 * p + 1][1] = r4[3];
            }
#pragma unroll
            for (int mt = 0; mt < 2; mt++)
#pragma unroll
                for (int nt = 0; nt < 8; nt++)
                    mma16816(c[mt][nt], ah[mt], bh[nt]);
        }
        __syncthreads();
    }

    // ---- epilogue ----
#pragma unroll
    for (int mt = 0; mt < 2; mt++) {
#pragma unroll
        for (int nt = 0; nt < 8; nt++) {
            int col = n0 + warp_n * 64 + nt * 8 + (lane & 3) * 2;
#pragma unroll
            for (int half = 0; half < 2; half++) {
                int m = warp_m * 32 + mt * 16 + (lane >> 2) + half * 8;
                int en = ent[m];
                if (en < 0) continue;
                float v0 = c[mt][nt][half * 2 + 0] + bias[e * Ntot + col];
                float v1 = c[mt][nt][half * 2 + 1] + bias[e * Ntot + col + 1];
                if (MODE == 0) {
                    float ga = 0.5f * v0 * (1.0f + erff(v0 * 0.7071067811865476f));
                    float gb = 0.5f * v1 * (1.0f + erff(v1 * 0.7071067811865476f));
                    __half2 h2 = __floats2half2_rn(ga, gb);
                    *(uint32_t*)(outh + (size_t)en * Hn + col) = *(uint32_t*)&h2;
                } else {
                    float g = gw[m];
                    int t = en >> 1;
                    atomicAdd(outf + (size_t)t * Dn + col, v0 * g);
                    atomicAdd(outf + (size_t)t * Dn + col + 1, v1 * g);
                }
            }
        }
    }
}

// ---------------- launch ----------------------------------------------------
extern "C" void kernel_launch(void* const* d_in, const int* in_sizes, int n_in,
                              void* d_out, int out_size) {
    const float* x   = (const float*)d_in[0];
    const float* mus = (const float*)d_in[1];
    const float* ls  = (const float*)d_in[2];
    const float* W1  = (const float*)d_in[3];
    const float* b1  = (const float*)d_in[4];
    const float* W2  = (const float*)d_in[5];
    const float* b2  = (const float*)d_in[6];
    float* out = (float*)d_out;

    const int Ny  = Nn * Dn;
    const int Nlp = Nn * En;
    const int Nti = Nn * Kn;
    int has_lp = (out_size >= Ny + Nlp) ? 1 : 0;
    int has_ti = (out_size >= Ny + Nlp + Nti) ? 1 : 0;
    float* out_lp = out + Ny;
    float* out_ti = out + Ny + Nlp;

    cudaFuncSetAttribute(gemm_mma<0>, cudaFuncAttributeMaxDynamicSharedMemorySize, NSTG * STG_BYTES);
    cudaFuncSetAttribute(gemm_mma<1>, cudaFuncAttributeMaxDynamicSharedMemorySize, NSTG * STG_BYTES);

    // zero the y region (gemm2 accumulates into it via RED)
    cudaMemsetAsync(out, 0, (size_t)Ny * sizeof(float));

    precompute_kernel<<<Bn * En, 256>>>(ls, mus);

    __half *w1, *w2, *hh, *xh;
    cudaGetSymbolAddress((void**)&w1, g_w1);
    cudaGetSymbolAddress((void**)&w2, g_w2);
    cudaGetSymbolAddress((void**)&hh, g_hh);
    cudaGetSymbolAddress((void**)&xh, g_xh);

    // W1 [E][D][H] -> [E][H][D]: R=Dn, C=Hn
    dim3 t1(Hn / 32, Dn / 64, En);
    transpose_kernel<<<t1, 256>>>(W1, w1, Dn, Hn);
    // W2 [E][H][D] -> [E][D][H]: R=Hn, C=Dn
    dim3 t2(Dn / 32, Hn / 64, En);
    transpose_kernel<<<t2, 256>>>(W2, w2, Hn, Dn);

    gate_kernel<<<Nn / 32, 256>>>(x, xh, out_lp, out_ti, has_lp, has_ti);

    dim3 g1(Hn / 128, Nn / 128, En);
    gemm_mma<0><<<g1, 256, NSTG * STG_BYTES>>>(xh, w1, b1, nullptr, hh);

    dim3 g2(Dn / 128, Nn / 128, En);
    gemm_mma<1><<<g2, 256, NSTG * STG_BYTES>>>(hh, w2, b2, out, nullptr);

    (void)in_sizes; (void)n_in;
}

// round 10
// speedup vs baseline: 1.4991x; 1.0352x over previous
#include <cuda_runtime.h>
#include <cuda_fp16.h>
#include <math.h>
#include <stdint.h>

// Problem dims
#define Bn 8
#define Tn 1024
#define Dn 512
#define Hn 1024
#define En 8
#define Kn 2
#define Nn (Bn * Tn)          // 8192 tokens
#define LOG_2PI 1.8378770664093453f

// ---------------- scratch (static __device__ globals) ----------------------
__device__ __half g_hh[(size_t)Nn * Kn * Hn];          // gelu(h) fp16, [slot][H]
__device__ __half g_xh[(size_t)Nn * Dn];               // x cast to fp16
__device__ float  g_gate[Nn * Kn];
__device__ int    g_counts[En];
__device__ int    g_list[En][Nn];
__device__ float2 g_tab[Bn * En * Dn];                 // (isig2, mu*isig2)
__device__ float  g_C[Bn * En];                        // per-(b,e) constant
__device__ __half g_w1[(size_t)En * Hn * Dn];          // W1^T [E][H][D] fp16
__device__ __half g_w2[(size_t)En * Dn * Hn];          // W2^T [E][D][H] fp16

// ---------------- helpers ---------------------------------------------------
__device__ __forceinline__ uint32_t smem_u32(const void* p) {
    uint32_t a;
    asm("{ .reg .u64 t; cvta.to.shared.u64 t, %1; cvt.u32.u64 %0, t; }" : "=r"(a) : "l"(p));
    return a;
}
__device__ __forceinline__ void ldsm4(uint32_t* r, uint32_t addr) {
    asm volatile("ldmatrix.sync.aligned.m8n8.x4.shared.b16 {%0,%1,%2,%3}, [%4];"
        : "=r"(r[0]), "=r"(r[1]), "=r"(r[2]), "=r"(r[3]) : "r"(addr));
}
__device__ __forceinline__ void mma16816(float* c, const uint32_t* a, const uint32_t* b) {
    asm volatile("mma.sync.aligned.m16n8k16.row.col.f32.f16.f16.f32 "
        "{%0,%1,%2,%3}, {%4,%5,%6,%7}, {%8,%9}, {%0,%1,%2,%3};"
        : "+f"(c[0]), "+f"(c[1]), "+f"(c[2]), "+f"(c[3])
        : "r"(a[0]), "r"(a[1]), "r"(a[2]), "r"(a[3]), "r"(b[0]), "r"(b[1]));
}
#define CPA16(dst, src) asm volatile("cp.async.cg.shared.global [%0], [%1], 16;" :: "r"(dst), "l"(src) : "memory")
#define CPC()  asm volatile("cp.async.commit_group;" ::: "memory")
#define CPW2() asm volatile("cp.async.wait_group 2;" ::: "memory")
#define CPW1() asm volatile("cp.async.wait_group 1;" ::: "memory")
#define CPW0() asm volatile("cp.async.wait_group 0;" ::: "memory")

// ---------------- kernel: precompute gate table + zero counts --------------
__global__ void precompute_kernel(const float* __restrict__ log_sigmas,
                                  const float* __restrict__ mus) {
    int be = blockIdx.x;              // b*En + e
    int tid = threadIdx.x;            // 256
    if (be == 0 && tid < En) g_counts[tid] = 0;
    __shared__ float red[256];
    float s = 0.0f;
    for (int d = tid; d < Dn; d += 256) {
        float ls = log_sigmas[be * Dn + d];
        float mu = mus[be * Dn + d];
        float s2 = __expf(-2.0f * ls);
        g_tab[be * Dn + d] = make_float2(s2, mu * s2);
        s += -0.5f * mu * mu * s2 - ls;
    }
    red[tid] = s;
    __syncthreads();
    for (int o = 128; o > 0; o >>= 1) {
        if (tid < o) red[tid] += red[tid + o];
        __syncthreads();
    }
    if (tid == 0) g_C[be] = red[0] - 0.5f * LOG_2PI * (float)Dn;
}

// ---------------- kernel: transpose to fp16 ---------------------------------
// src [E][R][C] fp32 -> dst [E][C][R] half. Tiles 64R x 32C, coalesced half2 out.
__global__ __launch_bounds__(256) void transpose_kernel(
        const float* __restrict__ src,
        __half* __restrict__ dst,
        int R, int C) {
    __shared__ float t[64][33];
    int e = blockIdx.z;
    int c0 = blockIdx.x * 32, r0 = blockIdx.y * 64;
    int tid = threadIdx.x;
    const float* s = src + (size_t)e * R * C;
#pragma unroll
    for (int p = 0; p < 8; p++) {
        int i = tid + p * 256;
        int r = i >> 5, c = i & 31;
        t[r][c] = s[(size_t)(r0 + r) * C + c0 + c];
    }
    __syncthreads();
    size_t obase = (size_t)e * C * R + r0;
#pragma unroll
    for (int p = 0; p < 4; p++) {
        int i = tid + p * 256;
        int oc = i >> 5, j = i & 31;
        __half2 h2 = __floats2half2_rn(t[2 * j][oc], t[2 * j + 1][oc]);
        *(uint32_t*)(dst + obase + (size_t)(c0 + oc) * R + 2 * j) = *(uint32_t*)&h2;
    }
}

// ---------------- kernel: gating + fused x->fp16 cast ----------------------
// 16 tokens per CTA (each of 8 warps handles 2 tokens). grid=512. Reg-trimmed.
__global__ __launch_bounds__(256, 3) void gate_kernel(const float* __restrict__ x,
                                                      __half* __restrict__ xh,
                                                      float* __restrict__ out_lp,
                                                      float* __restrict__ out_ti,
                                                      int has_lp, int has_ti) {
    __shared__ float2 stab[En * Dn];   // 32 KB
    int tid = threadIdx.x;
    int warp = tid >> 5, lane = tid & 31;
    int b = blockIdx.x >> 6;           // 64 CTAs per batch (1024 tokens / 16)

    for (int i = tid; i < En * Dn; i += 256) stab[i] = g_tab[b * En * Dn + i];
    __syncthreads();

#pragma unroll 1
    for (int tt = 0; tt < 2; tt++) {
        int t = blockIdx.x * 16 + warp * 2 + tt;

        float xr[16];
#pragma unroll
        for (int i = 0; i < 16; i++) xr[i] = x[t * Dn + lane + 32 * i];
#pragma unroll
        for (int i = 0; i < 16; i++)
            xh[t * Dn + lane + 32 * i] = __float2half_rn(xr[i]);

        float lp[En];
#pragma unroll
        for (int e = 0; e < En; e++) {
            const float2* tb = stab + e * Dn;
            float a1 = 0.0f, a2 = 0.0f;
#pragma unroll
            for (int i = 0; i < 16; i++) {
                float2 p = tb[lane + 32 * i];
                a1 = fmaf(xr[i] * p.x, xr[i], a1);   // x^2 * isig2 (no xr2 array)
                a2 = fmaf(xr[i], p.y, a2);
            }
            float sacc = a2 - 0.5f * a1;
#pragma unroll
            for (int o = 16; o > 0; o >>= 1) sacc += __shfl_xor_sync(0xffffffffu, sacc, o);
            lp[e] = sacc + g_C[b * En + e];
        }

        if (lane == 0) {
            int e0 = 0;
#pragma unroll
            for (int e = 1; e < En; e++) if (lp[e] > lp[e0]) e0 = e;
            int e1 = -1;
#pragma unroll
            for (int e = 0; e < En; e++) {
                if (e == e0) continue;
                if (e1 < 0 || lp[e] > lp[e1]) e1 = e;
            }
            float p1 = __expf(lp[e1] - lp[e0]);
            float inv = 1.0f / (1.0f + p1);
            g_gate[t * 2 + 0] = inv;
            g_gate[t * 2 + 1] = p1 * inv;
            int p = atomicAdd(&g_counts[e0], 1);
            g_list[e0][p] = (t << 1) | 0;
            p = atomicAdd(&g_counts[e1], 1);
            g_list[e1][p] = (t << 1) | 1;
            if (has_lp) {
#pragma unroll
                for (int e = 0; e < En; e++) out_lp[t * En + e] = lp[e];
            }
            if (has_ti) {
                out_ti[t * 2 + 0] = (float)e0;
                out_ti[t * 2 + 1] = (float)e1;
            }
        }
    }
}

// ---------------- warp-MMA grouped GEMM, 4-stage single-sync pipeline ------
// CTA 128x128, 8 warps (warp tile 32x64), K-step 32. Pure fp16 A and B.
// MODE 0: h = gelu(xh @ W1T + b1) -> g_hh fp16. K=512, N=1024, A row = en>>1.
// MODE 1: y[t] += gate*(g_hh @ W2T + b2) via RED. K=1024, N=512, A row = en.
#define ROWB 80
#define STG_BYTES (2 * 128 * ROWB)    // A + B per stage = 20480
#define NSTG 4
template <int MODE>
__global__ __launch_bounds__(256) void gemm_mma(const __half* __restrict__ Aglob,
                                                const __half* __restrict__ Bg,
                                                const float* __restrict__ bias,
                                                float* __restrict__ outf,
                                                __half* __restrict__ outh) {
    constexpr int Ktot = MODE ? Hn : Dn;
    constexpr int Ntot = MODE ? Dn : Hn;
    constexpr int NCH = Ktot / 32;

    int e = blockIdx.z;
    int cnt = g_counts[e];
    int row0 = blockIdx.y * 128;
    if (row0 >= cnt) return;
    int n0 = blockIdx.x * 128;

    extern __shared__ char sdyn[];
    __shared__ int ent[128];
    __shared__ int rowIdx[128];
    __shared__ float gw[128];

    int tid = threadIdx.x, lane = tid & 31, wid = tid >> 5;
    int warp_m = wid & 3, warp_n = wid >> 2;

    if (tid < 128) {
        int en = (row0 + tid < cnt) ? g_list[e][row0 + tid] : -1;
        ent[tid] = en;
        gw[tid] = (en >= 0) ? g_gate[en] : 0.0f;
        int safe = g_list[e][row0];
        int use = (en >= 0) ? en : safe;
        rowIdx[tid] = MODE ? use : (use >> 1);
    }
    __syncthreads();

    const __half* Be = Bg + (size_t)e * Ntot * Ktot + (size_t)n0 * Ktot;
    uint32_t sbase = smem_u32(sdyn);

    float c[2][8][4];
#pragma unroll
    for (int i = 0; i < 2; i++)
#pragma unroll
        for (int j = 0; j < 8; j++)
#pragma unroll
            for (int q = 0; q < 4; q++) c[i][j][q] = 0.0f;

    uint32_t a_row = (uint32_t)(lane & 15);
    uint32_t a_kh  = (uint32_t)((lane >> 4) << 3);
    uint32_t b_row = (uint32_t)((lane & 7) + ((lane >> 4) << 3));
    uint32_t b_kh  = (uint32_t)(lane & 8);

    auto prefetch = [&](int k0, int s) {
        uint32_t base = sbase + s * STG_BYTES;
#pragma unroll
        for (int j = 0; j < 2; j++) {
            int i = tid + 256 * j;
            int m = i >> 2, cc = i & 3;
            const __half* src = Aglob + (size_t)rowIdx[m] * Ktot + k0 + cc * 8;
            CPA16(base + m * ROWB + cc * 16, src);
        }
#pragma unroll
        for (int j = 0; j < 2; j++) {
            int i = tid + 256 * j;
            int n = i >> 2, cc = i & 3;
            CPA16(base + 128 * ROWB + n * ROWB + cc * 16, Be + (size_t)n * Ktot + k0 + cc * 8);
        }
    };

    prefetch(0, 0);
    CPC();
    prefetch(32, 1);
    CPC();

    for (int cc = 0; cc < NCH; cc++) {
        int s = cc % NSTG;
        if (cc + 2 < NCH) {
            prefetch((cc + 2) * 32, (cc + 2) % NSTG);
            CPC();
            CPW2();
        } else if (cc + 1 < NCH) {
            CPW1();
        } else {
            CPW0();
        }
        // single barrier per chunk: NSTG=4 guarantees the prefetch target
        // stage (cc+2)%4 == (cc-2)%4 was fully consumed (all warps passed
        // sync(cc-1), hence finished compute(cc-2)); wait_group above
        // guarantees stage cc landed before any thread reads it.
        __syncthreads();

        uint32_t baseA = sbase + s * STG_BYTES;
        uint32_t baseB = baseA + 128 * ROWB;
#pragma unroll
        for (int kk = 0; kk < 2; kk++) {
            uint32_t ka = (uint32_t)(kk * 32) + a_kh * 2;
            uint32_t ah[2][4];
#pragma unroll
            for (int mt = 0; mt < 2; mt++) {
                uint32_t ro = (uint32_t)(warp_m * 32 + mt * 16) + a_row;
                ldsm4(ah[mt], baseA + ro * ROWB + ka);
            }
            uint32_t kb = (uint32_t)(kk * 32) + b_kh * 2;
            uint32_t bh[8][2];
#pragma unroll
            for (int p = 0; p < 4; p++) {
                uint32_t ro = (uint32_t)(warp_n * 64 + p * 16) + b_row;
                uint32_t r4[4];
                ldsm4(r4, baseB + ro * ROWB + kb);
                bh[2 * p][0] = r4[0]; bh[2 * p][1] = r4[1];
                bh[2 * p + 1][0] = r4[2]; bh[2 * p + 1][1] = r4[3];
            }
#pragma unroll
            for (int mt = 0; mt < 2; mt++)
#pragma unroll
                for (int nt = 0; nt < 8; nt++)
                    mma16816(c[mt][nt], ah[mt], bh[nt]);
        }
    }

    __syncthreads();   // protect last-read stages before epilogue reuses nothing; cheap, once

    // ---- epilogue ----
#pragma unroll
    for (int mt = 0; mt < 2; mt++) {
#pragma unroll
        for (int nt = 0; nt < 8; nt++) {
            int col = n0 + warp_n * 64 + nt * 8 + (lane & 3) * 2;
#pragma unroll
            for (int half = 0; half < 2; half++) {
                int m = warp_m * 32 + mt * 16 + (lane >> 2) + half * 8;
                int en = ent[m];
                if (en < 0) continue;
                float v0 = c[mt][nt][half * 2 + 0] + bias[e * Ntot + col];
                float v1 = c[mt][nt][half * 2 + 1] + bias[e * Ntot + col + 1];
                if (MODE == 0) {
                    float ga = 0.5f * v0 * (1.0f + erff(v0 * 0.7071067811865476f));
                    float gb = 0.5f * v1 * (1.0f + erff(v1 * 0.7071067811865476f));
                    __half2 h2 = __floats2half2_rn(ga, gb);
                    *(uint32_t*)(outh + (size_t)en * Hn + col) = *(uint32_t*)&h2;
                } else {
                    float g = gw[m];
                    int t = en >> 1;
                    atomicAdd(outf + (size_t)t * Dn + col, v0 * g);
                    atomicAdd(outf + (size_t)t * Dn + col + 1, v1 * g);
                }
            }
        }
    }
}

// ---------------- launch ----------------------------------------------------
extern "C" void kernel_launch(void* const* d_in, const int* in_sizes, int n_in,
                              void* d_out, int out_size) {
    const float* x   = (const float*)d_in[0];
    const float* mus = (const float*)d_in[1];
    const float* ls  = (const float*)d_in[2];
    const float* W1  = (const float*)d_in[3];
    const float* b1  = (const float*)d_in[4];
    const float* W2  = (const float*)d_in[5];
    const float* b2  = (const float*)d_in[6];
    float* out = (float*)d_out;

    const int Ny  = Nn * Dn;
    const int Nlp = Nn * En;
    const int Nti = Nn * Kn;
    int has_lp = (out_size >= Ny + Nlp) ? 1 : 0;
    int has_ti = (out_size >= Ny + Nlp + Nti) ? 1 : 0;
    float* out_lp = out + Ny;
    float* out_ti = out + Ny + Nlp;

    cudaFuncSetAttribute(gemm_mma<0>, cudaFuncAttributeMaxDynamicSharedMemorySize, NSTG * STG_BYTES);
    cudaFuncSetAttribute(gemm_mma<1>, cudaFuncAttributeMaxDynamicSharedMemorySize, NSTG * STG_BYTES);

    // zero the y region (gemm2 accumulates into it via RED)
    cudaMemsetAsync(out, 0, (size_t)Ny * sizeof(float));

    precompute_kernel<<<Bn * En, 256>>>(ls, mus);

    __half *w1, *w2, *hh, *xh;
    cudaGetSymbolAddress((void**)&w1, g_w1);
    cudaGetSymbolAddress((void**)&w2, g_w2);
    cudaGetSymbolAddress((void**)&hh, g_hh);
    cudaGetSymbolAddress((void**)&xh, g_xh);

    // W1 [E][D][H] -> [E][H][D]: R=Dn, C=Hn
    dim3 t1(Hn / 32, Dn / 64, En);
    transpose_kernel<<<t1, 256>>>(W1, w1, Dn, Hn);
    // W2 [E][H][D] -> [E][D][H]: R=Hn, C=Dn
    dim3 t2(Dn / 32, Hn / 64, En);
    transpose_kernel<<<t2, 256>>>(W2, w2, Hn, Dn);

    gate_kernel<<<Nn / 16, 256>>>(x, xh, out_lp, out_ti, has_lp, has_ti);

    dim3 g1(Hn / 128, Nn / 128, En);
    gemm_mma<0><<<g1, 256, NSTG * STG_BYTES>>>(xh, w1, b1, nullptr, hh);

    dim3 g2(Dn / 128, Nn / 128, En);
    gemm_mma<1><<<g2, 256, NSTG * STG_BYTES>>>(hh, w2, b2, out, nullptr);

    (void)in_sizes; (void)n_in;
}

// round 11
// speedup vs baseline: 1.5575x; 1.0389x over previous
#include <cuda_runtime.h>
#include <cuda_fp16.h>
#include <math.h>
#include <stdint.h>

// Problem dims
#define Bn 8
#define Tn 1024
#define Dn 512
#define Hn 1024
#define En 8
#define Kn 2
#define Nn (Bn * Tn)          // 8192 tokens
#define LOG_2PI 1.8378770664093453f

// ---------------- scratch (static __device__ globals) ----------------------
__device__ __half g_hh[(size_t)Nn * Kn * Hn];          // gelu(h) fp16, [slot][H]
__device__ __half g_xh[(size_t)Nn * Dn];               // x cast to fp16
__device__ float  g_gate[Nn * Kn];
__device__ int    g_counts[En];
__device__ int    g_list[En][Nn];
__device__ __align__(16) float2 g_tab[Bn * En * Dn];   // (isig2, mu*isig2)
__device__ float  g_C[Bn * En];                        // per-(b,e) constant
__device__ __half g_w1[(size_t)En * Hn * Dn];          // W1^T [E][H][D] fp16
__device__ __half g_w2[(size_t)En * Dn * Hn];          // W2^T [E][D][H] fp16

// ---------------- helpers ---------------------------------------------------
__device__ __forceinline__ uint32_t smem_u32(const void* p) {
    uint32_t a;
    asm("{ .reg .u64 t; cvta.to.shared.u64 t, %1; cvt.u32.u64 %0, t; }" : "=r"(a) : "l"(p));
    return a;
}
__device__ __forceinline__ void ldsm4(uint32_t* r, uint32_t addr) {
    asm volatile("ldmatrix.sync.aligned.m8n8.x4.shared.b16 {%0,%1,%2,%3}, [%4];"
        : "=r"(r[0]), "=r"(r[1]), "=r"(r[2]), "=r"(r[3]) : "r"(addr));
}
__device__ __forceinline__ void mma16816(float* c, const uint32_t* a, const uint32_t* b) {
    asm volatile("mma.sync.aligned.m16n8k16.row.col.f32.f16.f16.f32 "
        "{%0,%1,%2,%3}, {%4,%5,%6,%7}, {%8,%9}, {%0,%1,%2,%3};"
        : "+f"(c[0]), "+f"(c[1]), "+f"(c[2]), "+f"(c[3])
        : "r"(a[0]), "r"(a[1]), "r"(a[2]), "r"(a[3]), "r"(b[0]), "r"(b[1]));
}
#define CPA16(dst, src) asm volatile("cp.async.cg.shared.global [%0], [%1], 16;" :: "r"(dst), "l"(src) : "memory")
#define CPC()  asm volatile("cp.async.commit_group;" ::: "memory")
#define CPW2() asm volatile("cp.async.wait_group 2;" ::: "memory")
#define CPW1() asm volatile("cp.async.wait_group 1;" ::: "memory")
#define CPW0() asm volatile("cp.async.wait_group 0;" ::: "memory")

// ---------------- kernel: precompute gate table + zero counts --------------
__global__ void precompute_kernel(const float* __restrict__ log_sigmas,
                                  const float* __restrict__ mus) {
    int be = blockIdx.x;              // b*En + e
    int tid = threadIdx.x;            // 256
    if (be == 0 && tid < En) g_counts[tid] = 0;
    __shared__ float red[256];
    float s = 0.0f;
    for (int d = tid; d < Dn; d += 256) {
        float ls = log_sigmas[be * Dn + d];
        float mu = mus[be * Dn + d];
        float s2 = __expf(-2.0f * ls);
        g_tab[be * Dn + d] = make_float2(s2, mu * s2);
        s += -0.5f * mu * mu * s2 - ls;
    }
    red[tid] = s;
    __syncthreads();
    for (int o = 128; o > 0; o >>= 1) {
        if (tid < o) red[tid] += red[tid + o];
        __syncthreads();
    }
    if (tid == 0) g_C[be] = red[0] - 0.5f * LOG_2PI * (float)Dn;
}

// ---------------- kernel: transpose to fp16 ---------------------------------
// src [E][R][C] fp32 -> dst [E][C][R] half. Tiles 64R x 32C, coalesced half2 out.
__global__ __launch_bounds__(256) void transpose_kernel(
        const float* __restrict__ src,
        __half* __restrict__ dst,
        int R, int C) {
    __shared__ float t[64][33];
    int e = blockIdx.z;
    int c0 = blockIdx.x * 32, r0 = blockIdx.y * 64;
    int tid = threadIdx.x;
    const float* s = src + (size_t)e * R * C;
#pragma unroll
    for (int p = 0; p < 8; p++) {
        int i = tid + p * 256;
        int r = i >> 5, c = i & 31;
        t[r][c] = s[(size_t)(r0 + r) * C + c0 + c];
    }
    __syncthreads();
    size_t obase = (size_t)e * C * R + r0;
#pragma unroll
    for (int p = 0; p < 4; p++) {
        int i = tid + p * 256;
        int oc = i >> 5, j = i & 31;
        __half2 h2 = __floats2half2_rn(t[2 * j][oc], t[2 * j + 1][oc]);
        *(uint32_t*)(dst + obase + (size_t)(c0 + oc) * R + 2 * j) = *(uint32_t*)&h2;
    }
}

// ---------------- kernel: gating + fused x->fp16 cast (v3) -----------------
// 16 tokens per CTA; each warp handles 2 tokens SIMULTANEOUSLY sharing table
// loads. Lane L owns d-pairs {2L+64i, 2L+1+64i} -> table reads are LDS.128.
__global__ __launch_bounds__(256, 3) void gate_kernel(const float* __restrict__ x,
                                                      __half* __restrict__ xh,
                                                      float* __restrict__ out_lp,
                                                      float* __restrict__ out_ti,
                                                      int has_lp, int has_ti) {
    __shared__ __align__(16) float2 stab[En * Dn];   // 32 KB
    int tid = threadIdx.x;
    int warp = tid >> 5, lane = tid & 31;
    int b = blockIdx.x >> 6;           // 64 CTAs per batch (1024 tokens / 16)

    {   // coalesced float4 table fill
        const float4* src = (const float4*)(g_tab + b * En * Dn);
        float4* dst = (float4*)stab;
        for (int i = tid; i < En * Dn / 2; i += 256) dst[i] = src[i];
    }
    __syncthreads();

    int t0 = blockIdx.x * 16 + warp * 2;
    int t1 = t0 + 1;

    float xr0[16], xr1[16];
#pragma unroll
    for (int i = 0; i < 8; i++) {
        float2 v0 = *(const float2*)(x + (size_t)t0 * Dn + lane * 2 + 64 * i);
        float2 v1 = *(const float2*)(x + (size_t)t1 * Dn + lane * 2 + 64 * i);
        xr0[2 * i] = v0.x; xr0[2 * i + 1] = v0.y;
        xr1[2 * i] = v1.x; xr1[2 * i + 1] = v1.y;
    }
#pragma unroll
    for (int i = 0; i < 8; i++) {
        __half2 h0 = __floats2half2_rn(xr0[2 * i], xr0[2 * i + 1]);
        __half2 h1 = __floats2half2_rn(xr1[2 * i], xr1[2 * i + 1]);
        *(uint32_t*)(xh + (size_t)t0 * Dn + lane * 2 + 64 * i) = *(uint32_t*)&h0;
        *(uint32_t*)(xh + (size_t)t1 * Dn + lane * 2 + 64 * i) = *(uint32_t*)&h1;
    }

    float lp0[En], lp1[En];
#pragma unroll
    for (int e = 0; e < En; e++) {
        const float4* tb = (const float4*)(stab + e * Dn);   // 2 entries per float4
        float a10 = 0.0f, a20 = 0.0f, a11 = 0.0f, a21 = 0.0f;
#pragma unroll
        for (int i = 0; i < 8; i++) {
            float4 p = tb[lane + 32 * i];   // (isig2_d0, muis_d0, isig2_d1, muis_d1)
            a10 = fmaf(xr0[2 * i] * p.x, xr0[2 * i], a10);
            a20 = fmaf(xr0[2 * i], p.y, a20);
            a10 = fmaf(xr0[2 * i + 1] * p.z, xr0[2 * i + 1], a10);
            a20 = fmaf(xr0[2 * i + 1], p.w, a20);
            a11 = fmaf(xr1[2 * i] * p.x, xr1[2 * i], a11);
            a21 = fmaf(xr1[2 * i], p.y, a21);
            a11 = fmaf(xr1[2 * i + 1] * p.z, xr1[2 * i + 1], a11);
            a21 = fmaf(xr1[2 * i + 1], p.w, a21);
        }
        float s0 = a20 - 0.5f * a10;
        float s1 = a21 - 0.5f * a11;
#pragma unroll
        for (int o = 16; o > 0; o >>= 1) {
            s0 += __shfl_xor_sync(0xffffffffu, s0, o);
            s1 += __shfl_xor_sync(0xffffffffu, s1, o);
        }
        float C = g_C[b * En + e];
        lp0[e] = s0 + C;
        lp1[e] = s1 + C;
    }

    // lanes 0 and 1 write back tokens t0 / t1 in parallel
    if (lane < 2) {
        int t = (lane == 0) ? t0 : t1;
        float lp[En];
#pragma unroll
        for (int e = 0; e < En; e++) lp[e] = (lane == 0) ? lp0[e] : lp1[e];
        int e0 = 0;
#pragma unroll
        for (int e = 1; e < En; e++) if (lp[e] > lp[e0]) e0 = e;
        int e1 = -1;
#pragma unroll
        for (int e = 0; e < En; e++) {
            if (e == e0) continue;
            if (e1 < 0 || lp[e] > lp[e1]) e1 = e;
        }
        float p1 = __expf(lp[e1] - lp[e0]);
        float inv = 1.0f / (1.0f + p1);
        g_gate[t * 2 + 0] = inv;
        g_gate[t * 2 + 1] = p1 * inv;
        int p = atomicAdd(&g_counts[e0], 1);
        g_list[e0][p] = (t << 1) | 0;
        p = atomicAdd(&g_counts[e1], 1);
        g_list[e1][p] = (t << 1) | 1;
        if (has_lp) {
#pragma unroll
            for (int e = 0; e < En; e++) out_lp[t * En + e] = lp[e];
        }
        if (has_ti) {
            out_ti[t * 2 + 0] = (float)e0;
            out_ti[t * 2 + 1] = (float)e1;
        }
    }
}

// ---------------- warp-MMA grouped GEMM, 4-stage single-sync pipeline ------
// CTA 128x128, 8 warps (warp tile 32x64), K-step 32. Pure fp16 A and B.
// MODE 0: h = gelu(xh @ W1T + b1) -> g_hh fp16. K=512, N=1024, A row = en>>1.
// MODE 1: y[t] += gate*(g_hh @ W2T + b2) via RED. K=1024, N=512, A row = en.
#define ROWB 80
#define STG_BYTES (2 * 128 * ROWB)    // A + B per stage = 20480
#define NSTG 4
template <int MODE>
__global__ __launch_bounds__(256) void gemm_mma(const __half* __restrict__ Aglob,
                                                const __half* __restrict__ Bg,
                                                const float* __restrict__ bias,
                                                float* __restrict__ outf,
                                                __half* __restrict__ outh) {
    constexpr int Ktot = MODE ? Hn : Dn;
    constexpr int Ntot = MODE ? Dn : Hn;
    constexpr int NCH = Ktot / 32;

    int e = blockIdx.z;
    int cnt = g_counts[e];
    int row0 = blockIdx.y * 128;
    if (row0 >= cnt) return;
    int n0 = blockIdx.x * 128;

    extern __shared__ char sdyn[];
    __shared__ int ent[128];
    __shared__ int rowIdx[128];
    __shared__ float gw[128];

    int tid = threadIdx.x, lane = tid & 31, wid = tid >> 5;
    int warp_m = wid & 3, warp_n = wid >> 2;

    if (tid < 128) {
        int en = (row0 + tid < cnt) ? g_list[e][row0 + tid] : -1;
        ent[tid] = en;
        gw[tid] = (en >= 0) ? g_gate[en] : 0.0f;
        int safe = g_list[e][row0];
        int use = (en >= 0) ? en : safe;
        rowIdx[tid] = MODE ? use : (use >> 1);
    }
    __syncthreads();

    const __half* Be = Bg + (size_t)e * Ntot * Ktot + (size_t)n0 * Ktot;
    uint32_t sbase = smem_u32(sdyn);

    float c[2][8][4];
#pragma unroll
    for (int i = 0; i < 2; i++)
#pragma unroll
        for (int j = 0; j < 8; j++)
#pragma unroll
            for (int q = 0; q < 4; q++) c[i][j][q] = 0.0f;

    uint32_t a_row = (uint32_t)(lane & 15);
    uint32_t a_kh  = (uint32_t)((lane >> 4) << 3);
    uint32_t b_row = (uint32_t)((lane & 7) + ((lane >> 4) << 3));
    uint32_t b_kh  = (uint32_t)(lane & 8);

    auto prefetch = [&](int k0, int s) {
        uint32_t base = sbase + s * STG_BYTES;
#pragma unroll
        for (int j = 0; j < 2; j++) {
            int i = tid + 256 * j;
            int m = i >> 2, cc = i & 3;
            const __half* src = Aglob + (size_t)rowIdx[m] * Ktot + k0 + cc * 8;
            CPA16(base + m * ROWB + cc * 16, src);
        }
#pragma unroll
        for (int j = 0; j < 2; j++) {
            int i = tid + 256 * j;
            int n = i >> 2, cc = i & 3;
            CPA16(base + 128 * ROWB + n * ROWB + cc * 16, Be + (size_t)n * Ktot + k0 + cc * 8);
        }
    };

    prefetch(0, 0);
    CPC();
    prefetch(32, 1);
    CPC();

    for (int cc = 0; cc < NCH; cc++) {
        int s = cc % NSTG;
        if (cc + 2 < NCH) {
            prefetch((cc + 2) * 32, (cc + 2) % NSTG);
            CPC();
            CPW2();
        } else if (cc + 1 < NCH) {
            CPW1();
        } else {
            CPW0();
        }
        // single barrier per chunk: NSTG=4 guarantees the prefetch target
        // stage (cc+2)%4 == (cc-2)%4 was fully consumed before overwrite.
        __syncthreads();

        uint32_t baseA = sbase + s * STG_BYTES;
        uint32_t baseB = baseA + 128 * ROWB;
#pragma unroll
        for (int kk = 0; kk < 2; kk++) {
            uint32_t ka = (uint32_t)(kk * 32) + a_kh * 2;
            uint32_t ah[2][4];
#pragma unroll
            for (int mt = 0; mt < 2; mt++) {
                uint32_t ro = (uint32_t)(warp_m * 32 + mt * 16) + a_row;
                ldsm4(ah[mt], baseA + ro * ROWB + ka);
            }
            uint32_t kb = (uint32_t)(kk * 32) + b_kh * 2;
            uint32_t bh[8][2];
#pragma unroll
            for (int p = 0; p < 4; p++) {
                uint32_t ro = (uint32_t)(warp_n * 64 + p * 16) + b_row;
                uint32_t r4[4];
                ldsm4(r4, baseB + ro * ROWB + kb);
                bh[2 * p][0] = r4[0]; bh[2 * p][1] = r4[1];
                bh[2 * p + 1][0] = r4[2]; bh[2 * p + 1][1] = r4[3];
            }
#pragma unroll
            for (int mt = 0; mt < 2; mt++)
#pragma unroll
                for (int nt = 0; nt < 8; nt++)
                    mma16816(c[mt][nt], ah[mt], bh[nt]);
        }
    }

    __syncthreads();

    // ---- epilogue ----
#pragma unroll
    for (int mt = 0; mt < 2; mt++) {
#pragma unroll
        for (int nt = 0; nt < 8; nt++) {
            int col = n0 + warp_n * 64 + nt * 8 + (lane & 3) * 2;
#pragma unroll
            for (int half = 0; half < 2; half++) {
                int m = warp_m * 32 + mt * 16 + (lane >> 2) + half * 8;
                int en = ent[m];
                if (en < 0) continue;
                float v0 = c[mt][nt][half * 2 + 0] + bias[e * Ntot + col];
                float v1 = c[mt][nt][half * 2 + 1] + bias[e * Ntot + col + 1];
                if (MODE == 0) {
                    float ga = 0.5f * v0 * (1.0f + erff(v0 * 0.7071067811865476f));
                    float gb = 0.5f * v1 * (1.0f + erff(v1 * 0.7071067811865476f));
                    __half2 h2 = __floats2half2_rn(ga, gb);
                    *(uint32_t*)(outh + (size_t)en * Hn + col) = *(uint32_t*)&h2;
                } else {
                    float g = gw[m];
                    int t = en >> 1;
                    atomicAdd(outf + (size_t)t * Dn + col, v0 * g);
                    atomicAdd(outf + (size_t)t * Dn + col + 1, v1 * g);
                }
            }
        }
    }
}

// ---------------- launch ----------------------------------------------------
extern "C" void kernel_launch(void* const* d_in, const int* in_sizes, int n_in,
                              void* d_out, int out_size) {
    const float* x   = (const float*)d_in[0];
    const float* mus = (const float*)d_in[1];
    const float* ls  = (const float*)d_in[2];
    const float* W1  = (const float*)d_in[3];
    const float* b1  = (const float*)d_in[4];
    const float* W2  = (const float*)d_in[5];
    const float* b2  = (const float*)d_in[6];
    float* out = (float*)d_out;

    const int Ny  = Nn * Dn;
    const int Nlp = Nn * En;
    const int Nti = Nn * Kn;
    int has_lp = (out_size >= Ny + Nlp) ? 1 : 0;
    int has_ti = (out_size >= Ny + Nlp + Nti) ? 1 : 0;
    float* out_lp = out + Ny;
    float* out_ti = out + Ny + Nlp;

    cudaFuncSetAttribute(gemm_mma<0>, cudaFuncAttributeMaxDynamicSharedMemorySize, NSTG * STG_BYTES);
    cudaFuncSetAttribute(gemm_mma<1>, cudaFuncAttributeMaxDynamicSharedMemorySize, NSTG * STG_BYTES);

    // zero the y region (gemm2 accumulates into it via RED)
    cudaMemsetAsync(out, 0, (size_t)Ny * sizeof(float));

    precompute_kernel<<<Bn * En, 256>>>(ls, mus);

    __half *w1, *w2, *hh, *xh;
    cudaGetSymbolAddress((void**)&w1, g_w1);
    cudaGetSymbolAddress((void**)&w2, g_w2);
    cudaGetSymbolAddress((void**)&hh, g_hh);
    cudaGetSymbolAddress((void**)&xh, g_xh);

    // W1 [E][D][H] -> [E][H][D]: R=Dn, C=Hn
    dim3 t1(Hn / 32, Dn / 64, En);
    transpose_kernel<<<t1, 256>>>(W1, w1, Dn, Hn);
    // W2 [E][H][D] -> [E][D][H]: R=Hn, C=Dn
    dim3 t2(Dn / 32, Hn / 64, En);
    transpose_kernel<<<t2, 256>>>(W2, w2, Hn, Dn);

    gate_kernel<<<Nn / 16, 256>>>(x, xh, out_lp, out_ti, has_lp, has_ti);

    dim3 g1(Hn / 128, Nn / 128, En);
    gemm_mma<0><<<g1, 256, NSTG * STG_BYTES>>>(xh, w1, b1, nullptr, hh);

    dim3 g2(Dn / 128, Nn / 128, En);
    gemm_mma<1><<<g2, 256, NSTG * STG_BYTES>>>(hh, w2, b2, out, nullptr);

    (void)in_sizes; (void)n_in;
}

// round 12
// speedup vs baseline: 1.6830x; 1.0806x over previous
#include <cuda_runtime.h>
#include <cuda_fp16.h>
#include <math.h>
#include <stdint.h>

// Problem dims
#define Bn 8
#define Tn 1024
#define Dn 512
#define Hn 1024
#define En 8
#define Kn 2
#define Nn (Bn * Tn)          // 8192 tokens
#define LOG_2PI 1.8378770664093453f

// ---------------- scratch (static __device__ globals) ----------------------
__device__ __half g_hh[(size_t)Nn * Kn * Hn];          // gelu(h) fp16, [slot][H]
__device__ __half g_xh[(size_t)Nn * Dn];               // x cast to fp16
__device__ float  g_gate[Nn * Kn];
__device__ int    g_counts[En];
__device__ int    g_list[En][Nn];
__device__ __align__(16) float2 g_tab[Bn * En * Dn];   // (isig2, mu*isig2)
__device__ float  g_C[Bn * En];                        // per-(b,e) constant
__device__ __half g_w1[(size_t)En * Dn * Hn];          // W1 [E][D][H] fp16 (k-major)
__device__ __half g_w2[(size_t)En * Hn * Dn];          // W2 [E][H][D] fp16 (k-major)

// ---------------- helpers ---------------------------------------------------
__device__ __forceinline__ uint32_t smem_u32(const void* p) {
    uint32_t a;
    asm("{ .reg .u64 t; cvta.to.shared.u64 t, %1; cvt.u32.u64 %0, t; }" : "=r"(a) : "l"(p));
    return a;
}
__device__ __forceinline__ void ldsm4(uint32_t* r, uint32_t addr) {
    asm volatile("ldmatrix.sync.aligned.m8n8.x4.shared.b16 {%0,%1,%2,%3}, [%4];"
        : "=r"(r[0]), "=r"(r[1]), "=r"(r[2]), "=r"(r[3]) : "r"(addr));
}
__device__ __forceinline__ void ldsm4t(uint32_t* r, uint32_t addr) {
    asm volatile("ldmatrix.sync.aligned.m8n8.x4.trans.shared.b16 {%0,%1,%2,%3}, [%4];"
        : "=r"(r[0]), "=r"(r[1]), "=r"(r[2]), "=r"(r[3]) : "r"(addr));
}
__device__ __forceinline__ void mma16816(float* c, const uint32_t* a, const uint32_t* b) {
    asm volatile("mma.sync.aligned.m16n8k16.row.col.f32.f16.f16.f32 "
        "{%0,%1,%2,%3}, {%4,%5,%6,%7}, {%8,%9}, {%0,%1,%2,%3};"
        : "+f"(c[0]), "+f"(c[1]), "+f"(c[2]), "+f"(c[3])
        : "r"(a[0]), "r"(a[1]), "r"(a[2]), "r"(a[3]), "r"(b[0]), "r"(b[1]));
}
#define CPA16(dst, src) asm volatile("cp.async.cg.shared.global [%0], [%1], 16;" :: "r"(dst), "l"(src) : "memory")
#define CPC()  asm volatile("cp.async.commit_group;" ::: "memory")
#define CPW2() asm volatile("cp.async.wait_group 2;" ::: "memory")
#define CPW1() asm volatile("cp.async.wait_group 1;" ::: "memory")
#define CPW0() asm volatile("cp.async.wait_group 0;" ::: "memory")

// ---------------- kernel: precompute gate table + zero counts --------------
__global__ void precompute_kernel(const float* __restrict__ log_sigmas,
                                  const float* __restrict__ mus) {
    int be = blockIdx.x;              // b*En + e
    int tid = threadIdx.x;            // 256
    if (be == 0 && tid < En) g_counts[tid] = 0;
    __shared__ float red[256];
    float s = 0.0f;
    for (int d = tid; d < Dn; d += 256) {
        float ls = log_sigmas[be * Dn + d];
        float mu = mus[be * Dn + d];
        float s2 = __expf(-2.0f * ls);
        g_tab[be * Dn + d] = make_float2(s2, mu * s2);
        s += -0.5f * mu * mu * s2 - ls;
    }
    red[tid] = s;
    __syncthreads();
    for (int o = 128; o > 0; o >>= 1) {
        if (tid < o) red[tid] += red[tid + o];
        __syncthreads();
    }
    if (tid == 0) g_C[be] = red[0] - 0.5f * LOG_2PI * (float)Dn;
}

// ---------------- kernel: cast W1+W2 to fp16 (no transpose) ----------------
__global__ __launch_bounds__(256) void cast2_kernel(const float* __restrict__ W1,
                                                    const float* __restrict__ W2,
                                                    __half* __restrict__ o1,
                                                    __half* __restrict__ o2) {
    int i = blockIdx.x * 256 + threadIdx.x;     // float4 index
    const int n4 = En * Dn * Hn / 4;            // 1048576
    if (i >= n4) return;
    float4 a = ((const float4*)W1)[i];
    float4 b = ((const float4*)W2)[i];
    __half2 a0 = __floats2half2_rn(a.x, a.y), a1 = __floats2half2_rn(a.z, a.w);
    __half2 b0 = __floats2half2_rn(b.x, b.y), b1 = __floats2half2_rn(b.z, b.w);
    uint2 pa, pb;
    pa.x = *(uint32_t*)&a0; pa.y = *(uint32_t*)&a1;
    pb.x = *(uint32_t*)&b0; pb.y = *(uint32_t*)&b1;
    ((uint2*)o1)[i] = pa;
    ((uint2*)o2)[i] = pb;
}

// ---------------- kernel: gating + fused x->fp16 cast ----------------------
// 16 tokens per CTA; each warp handles 2 tokens sharing LDS.128 table loads.
// Reductions hoisted into one block: 16 independent shfl chains interleave.
__global__ __launch_bounds__(256, 3) void gate_kernel(const float* __restrict__ x,
                                                      __half* __restrict__ xh,
                                                      float* __restrict__ out_lp,
                                                      float* __restrict__ out_ti,
                                                      int has_lp, int has_ti) {
    __shared__ __align__(16) float2 stab[En * Dn];   // 32 KB
    int tid = threadIdx.x;
    int warp = tid >> 5, lane = tid & 31;
    int b = blockIdx.x >> 6;           // 64 CTAs per batch

    {   // coalesced float4 table fill
        const float4* src = (const float4*)(g_tab + b * En * Dn);
        float4* dst = (float4*)stab;
        for (int i = tid; i < En * Dn / 2; i += 256) dst[i] = src[i];
    }
    __syncthreads();

    int t0 = blockIdx.x * 16 + warp * 2;
    int t1 = t0 + 1;

    float xr0[16], xr1[16];
#pragma unroll
    for (int i = 0; i < 8; i++) {
        float2 v0 = *(const float2*)(x + (size_t)t0 * Dn + lane * 2 + 64 * i);
        float2 v1 = *(const float2*)(x + (size_t)t1 * Dn + lane * 2 + 64 * i);
        xr0[2 * i] = v0.x; xr0[2 * i + 1] = v0.y;
        xr1[2 * i] = v1.x; xr1[2 * i + 1] = v1.y;
    }
#pragma unroll
    for (int i = 0; i < 8; i++) {
        __half2 h0 = __floats2half2_rn(xr0[2 * i], xr0[2 * i + 1]);
        __half2 h1 = __floats2half2_rn(xr1[2 * i], xr1[2 * i + 1]);
        *(uint32_t*)(xh + (size_t)t0 * Dn + lane * 2 + 64 * i) = *(uint32_t*)&h0;
        *(uint32_t*)(xh + (size_t)t1 * Dn + lane * 2 + 64 * i) = *(uint32_t*)&h1;
    }

    float s0[En], s1[En];
#pragma unroll
    for (int e = 0; e < En; e++) {
        const float4* tb = (const float4*)(stab + e * Dn);
        float a10 = 0.0f, a20 = 0.0f, a11 = 0.0f, a21 = 0.0f;
#pragma unroll
        for (int i = 0; i < 8; i++) {
            float4 p = tb[lane + 32 * i];
            a10 = fmaf(xr0[2 * i] * p.x, xr0[2 * i], a10);
            a20 = fmaf(xr0[2 * i], p.y, a20);
            a10 = fmaf(xr0[2 * i + 1] * p.z, xr0[2 * i + 1], a10);
            a20 = fmaf(xr0[2 * i + 1], p.w, a20);
            a11 = fmaf(xr1[2 * i] * p.x, xr1[2 * i], a11);
            a21 = fmaf(xr1[2 * i], p.y, a21);
            a11 = fmaf(xr1[2 * i + 1] * p.z, xr1[2 * i + 1], a11);
            a21 = fmaf(xr1[2 * i + 1], p.w, a21);
        }
        s0[e] = a20 - 0.5f * a10;
        s1[e] = a21 - 0.5f * a11;
    }
    // 16 independent butterfly chains — hoisted for ILP
#pragma unroll
    for (int o = 16; o > 0; o >>= 1) {
#pragma unroll
        for (int e = 0; e < En; e++) {
            s0[e] += __shfl_xor_sync(0xffffffffu, s0[e], o);
            s1[e] += __shfl_xor_sync(0xffffffffu, s1[e], o);
        }
    }

    if (lane < 2) {
        int t = (lane == 0) ? t0 : t1;
        float lp[En];
#pragma unroll
        for (int e = 0; e < En; e++)
            lp[e] = ((lane == 0) ? s0[e] : s1[e]) + g_C[b * En + e];
        int e0 = 0;
#pragma unroll
        for (int e = 1; e < En; e++) if (lp[e] > lp[e0]) e0 = e;
        int e1 = -1;
#pragma unroll
        for (int e = 0; e < En; e++) {
            if (e == e0) continue;
            if (e1 < 0 || lp[e] > lp[e1]) e1 = e;
        }
        float p1 = __expf(lp[e1] - lp[e0]);
        float inv = 1.0f / (1.0f + p1);
        g_gate[t * 2 + 0] = inv;
        g_gate[t * 2 + 1] = p1 * inv;
        int p = atomicAdd(&g_counts[e0], 1);
        g_list[e0][p] = (t << 1) | 0;
        p = atomicAdd(&g_counts[e1], 1);
        g_list[e1][p] = (t << 1) | 1;
        if (has_lp) {
#pragma unroll
            for (int e = 0; e < En; e++) out_lp[t * En + e] = lp[e];
        }
        if (has_ti) {
            out_ti[t * 2 + 0] = (float)e0;
            out_ti[t * 2 + 1] = (float)e1;
        }
    }
}

// ---------------- warp-MMA grouped GEMM, 4-stage single-sync pipeline ------
// CTA 128x128, 8 warps (warp tile 32x64), K-step 32. fp16 A (m-major) and
// B loaded DIRECTLY from k-major weights via ldmatrix.trans (no transpose).
// MODE 0: h = gelu(xh @ W1 + b1) -> g_hh fp16. K=512, N=1024, A row = en>>1.
// MODE 1: y[t] += gate*(g_hh @ W2 + b2) via RED. K=1024, N=512, A row = en.
#define ROWB_A 80
#define ROWB_B 272                     // 128 n * 2B + 16 pad; bank-stride 4
#define STG_A (128 * ROWB_A)           // 10240
#define STG_B (32 * ROWB_B)            // 8704
#define STG_BYTES (STG_A + STG_B)      // 18944
#define NSTG 4
template <int MODE>
__global__ __launch_bounds__(256) void gemm_mma(const __half* __restrict__ Aglob,
                                                const __half* __restrict__ Bg,
                                                const float* __restrict__ bias,
                                                float* __restrict__ outf,
                                                __half* __restrict__ outh) {
    constexpr int Ktot = MODE ? Hn : Dn;
    constexpr int Ntot = MODE ? Dn : Hn;
    constexpr int NCH = Ktot / 32;

    int e = blockIdx.z;
    int cnt = g_counts[e];
    int row0 = blockIdx.y * 128;
    if (row0 >= cnt) return;
    int n0 = blockIdx.x * 128;

    extern __shared__ char sdyn[];
    __shared__ int ent[128];
    __shared__ int rowIdx[128];
    __shared__ float gw[128];

    int tid = threadIdx.x, lane = tid & 31, wid = tid >> 5;
    int warp_m = wid & 3, warp_n = wid >> 2;

    if (tid < 128) {
        int en = (row0 + tid < cnt) ? g_list[e][row0 + tid] : -1;
        ent[tid] = en;
        gw[tid] = (en >= 0) ? g_gate[en] : 0.0f;
        int safe = g_list[e][row0];
        int use = (en >= 0) ? en : safe;
        rowIdx[tid] = MODE ? use : (use >> 1);
    }
    __syncthreads();

    // weights are [E][Ktot][Ntot] k-major
    const __half* Be = Bg + (size_t)e * Ktot * Ntot + n0;
    uint32_t sbase = smem_u32(sdyn);

    float c[2][8][4];
#pragma unroll
    for (int i = 0; i < 2; i++)
#pragma unroll
        for (int j = 0; j < 8; j++)
#pragma unroll
            for (int q = 0; q < 4; q++) c[i][j][q] = 0.0f;

    uint32_t a_row = (uint32_t)(lane & 15);
    uint32_t a_kh  = (uint32_t)((lane >> 4) << 3);
    // trans-B lane map: k row = (lane&7)+(lane&8), n col = (lane>>4)*8
    uint32_t b_krow = (uint32_t)((lane & 7) + (lane & 8));
    uint32_t b_ncol = (uint32_t)((lane >> 4) << 3);

    auto prefetch = [&](int k0, int s) {
        uint32_t base = sbase + s * STG_BYTES;
#pragma unroll
        for (int j = 0; j < 2; j++) {           // A: 128 rows x 4 chunks
            int i = tid + 256 * j;
            int m = i >> 2, cc = i & 3;
            const __half* src = Aglob + (size_t)rowIdx[m] * Ktot + k0 + cc * 8;
            CPA16(base + m * ROWB_A + cc * 16, src);
        }
        uint32_t baseB = base + STG_A;
#pragma unroll
        for (int j = 0; j < 2; j++) {           // B: 32 k-rows x 16 chunks
            int i = tid + 256 * j;
            int r = i >> 4, cc = i & 15;
            const __half* src = Be + (size_t)(k0 + r) * Ntot + cc * 8;
            CPA16(baseB + r * ROWB_B + cc * 16, src);
        }
    };

    prefetch(0, 0);
    CPC();
    prefetch(32, 1);
    CPC();

    for (int cc = 0; cc < NCH; cc++) {
        int s = cc % NSTG;
        if (cc + 2 < NCH) {
            prefetch((cc + 2) * 32, (cc + 2) % NSTG);
            CPC();
            CPW2();
        } else if (cc + 1 < NCH) {
            CPW1();
        } else {
            CPW0();
        }
        // single barrier per chunk: NSTG=4 guarantees the prefetch target
        // stage was fully consumed before overwrite.
        __syncthreads();

        uint32_t baseA = sbase + s * STG_BYTES;
        uint32_t baseB = baseA + STG_A;
#pragma unroll
        for (int kk = 0; kk < 2; kk++) {
            uint32_t ka = (uint32_t)(kk * 32) + a_kh * 2;
            uint32_t ah[2][4];
#pragma unroll
            for (int mt = 0; mt < 2; mt++) {
                uint32_t ro = (uint32_t)(warp_m * 32 + mt * 16) + a_row;
                ldsm4(ah[mt], baseA + ro * ROWB_A + ka);
            }
            uint32_t bh[8][2];
#pragma unroll
            for (int p = 0; p < 4; p++) {
                uint32_t addr = baseB + (kk * 16 + b_krow) * ROWB_B
                              + (uint32_t)(warp_n * 64 + p * 16 + b_ncol) * 2;
                uint32_t r4[4];
                ldsm4t(r4, addr);
                bh[2 * p][0] = r4[0]; bh[2 * p][1] = r4[1];
                bh[2 * p + 1][0] = r4[2]; bh[2 * p + 1][1] = r4[3];
            }
#pragma unroll
            for (int mt = 0; mt < 2; mt++)
#pragma unroll
                for (int nt = 0; nt < 8; nt++)
                    mma16816(c[mt][nt], ah[mt], bh[nt]);
        }
    }

    __syncthreads();

    // ---- epilogue ----
#pragma unroll
    for (int mt = 0; mt < 2; mt++) {
#pragma unroll
        for (int nt = 0; nt < 8; nt++) {
            int col = n0 + warp_n * 64 + nt * 8 + (lane & 3) * 2;
#pragma unroll
            for (int half = 0; half < 2; half++) {
                int m = warp_m * 32 + mt * 16 + (lane >> 2) + half * 8;
                int en = ent[m];
                if (en < 0) continue;
                float v0 = c[mt][nt][half * 2 + 0] + bias[e * Ntot + col];
                float v1 = c[mt][nt][half * 2 + 1] + bias[e * Ntot + col + 1];
                if (MODE == 0) {
                    float ga = 0.5f * v0 * (1.0f + erff(v0 * 0.7071067811865476f));
                    float gb = 0.5f * v1 * (1.0f + erff(v1 * 0.7071067811865476f));
                    __half2 h2 = __floats2half2_rn(ga, gb);
                    *(uint32_t*)(outh + (size_t)en * Hn + col) = *(uint32_t*)&h2;
                } else {
                    float g = gw[m];
                    int t = en >> 1;
                    atomicAdd(outf + (size_t)t * Dn + col, v0 * g);
                    atomicAdd(outf + (size_t)t * Dn + col + 1, v1 * g);
                }
            }
        }
    }
}

// ---------------- launch ----------------------------------------------------
extern "C" void kernel_launch(void* const* d_in, const int* in_sizes, int n_in,
                              void* d_out, int out_size) {
    const float* x   = (const float*)d_in[0];
    const float* mus = (const float*)d_in[1];
    const float* ls  = (const float*)d_in[2];
    const float* W1  = (const float*)d_in[3];
    const float* b1  = (const float*)d_in[4];
    const float* W2  = (const float*)d_in[5];
    const float* b2  = (const float*)d_in[6];
    float* out = (float*)d_out;

    const int Ny  = Nn * Dn;
    const int Nlp = Nn * En;
    const int Nti = Nn * Kn;
    int has_lp = (out_size >= Ny + Nlp) ? 1 : 0;
    int has_ti = (out_size >= Ny + Nlp + Nti) ? 1 : 0;
    float* out_lp = out + Ny;
    float* out_ti = out + Ny + Nlp;

    cudaFuncSetAttribute(gemm_mma<0>, cudaFuncAttributeMaxDynamicSharedMemorySize, NSTG * STG_BYTES);
    cudaFuncSetAttribute(gemm_mma<1>, cudaFuncAttributeMaxDynamicSharedMemorySize, NSTG * STG_BYTES);

    // zero the y region (gemm2 accumulates into it via RED)
    cudaMemsetAsync(out, 0, (size_t)Ny * sizeof(float));

    precompute_kernel<<<Bn * En, 256>>>(ls, mus);

    __half *w1, *w2, *hh, *xh;
    cudaGetSymbolAddress((void**)&w1, g_w1);
    cudaGetSymbolAddress((void**)&w2, g_w2);
    cudaGetSymbolAddress((void**)&hh, g_hh);
    cudaGetSymbolAddress((void**)&xh, g_xh);

    cast2_kernel<<<(En * Dn * Hn / 4 + 255) / 256, 256>>>(W1, W2, w1, w2);

    gate_kernel<<<Nn / 16, 256>>>(x, xh, out_lp, out_ti, has_lp, has_ti);

    dim3 g1(Hn / 128, Nn / 128, En);
    gemm_mma<0><<<g1, 256, NSTG * STG_BYTES>>>(xh, w1, b1, nullptr, hh);

    dim3 g2(Dn / 128, Nn / 128, En);
    gemm_mma<1><<<g2, 256, NSTG * STG_BYTES>>>(hh, w2, b2, out, nullptr);

    (void)in_sizes; (void)n_in;
}

// round 13
// speedup vs baseline: 1.7361x; 1.0315x over previous
#include <cuda_runtime.h>
#include <cuda_fp16.h>
#include <math.h>
#include <stdint.h>

// Problem dims
#define Bn 8
#define Tn 1024
#define Dn 512
#define Hn 1024
#define En 8
#define Kn 2
#define Nn (Bn * Tn)          // 8192 tokens
#define LOG_2PI 1.8378770664093453f

// ---------------- scratch (static __device__ globals) ----------------------
__device__ __half g_hh[(size_t)Nn * Kn * Hn];          // gelu(h) fp16, [slot][H]
__device__ __half g_xh[(size_t)Nn * Dn];               // x cast to fp16
__device__ float  g_gate[Nn * Kn];
__device__ int    g_counts[En];
__device__ int    g_list[En][Nn];
__device__ __align__(16) float2 g_tab[Bn * En * Dn];   // (isig2, mu*isig2)
__device__ float  g_C[Bn * En];                        // per-(b,e) constant
__device__ __half g_w1[(size_t)En * Dn * Hn];          // W1 [E][D][H] fp16 (k-major)
__device__ __half g_w2[(size_t)En * Hn * Dn];          // W2 [E][H][D] fp16 (k-major)

// ---------------- helpers ---------------------------------------------------
__device__ __forceinline__ uint32_t smem_u32(const void* p) {
    uint32_t a;
    asm("{ .reg .u64 t; cvta.to.shared.u64 t, %1; cvt.u32.u64 %0, t; }" : "=r"(a) : "l"(p));
    return a;
}
__device__ __forceinline__ void ldsm4(uint32_t* r, uint32_t addr) {
    asm volatile("ldmatrix.sync.aligned.m8n8.x4.shared.b16 {%0,%1,%2,%3}, [%4];"
        : "=r"(r[0]), "=r"(r[1]), "=r"(r[2]), "=r"(r[3]) : "r"(addr));
}
__device__ __forceinline__ void ldsm4t(uint32_t* r, uint32_t addr) {
    asm volatile("ldmatrix.sync.aligned.m8n8.x4.trans.shared.b16 {%0,%1,%2,%3}, [%4];"
        : "=r"(r[0]), "=r"(r[1]), "=r"(r[2]), "=r"(r[3]) : "r"(addr));
}
__device__ __forceinline__ void mma16816(float* c, const uint32_t* a, const uint32_t* b) {
    asm volatile("mma.sync.aligned.m16n8k16.row.col.f32.f16.f16.f32 "
        "{%0,%1,%2,%3}, {%4,%5,%6,%7}, {%8,%9}, {%0,%1,%2,%3};"
        : "+f"(c[0]), "+f"(c[1]), "+f"(c[2]), "+f"(c[3])
        : "r"(a[0]), "r"(a[1]), "r"(a[2]), "r"(a[3]), "r"(b[0]), "r"(b[1]));
}
__device__ __forceinline__ void red2(float* ptr, float v0, float v1) {
    asm volatile("red.global.add.v2.f32 [%0], {%1, %2};"
        :: "l"(ptr), "f"(v0), "f"(v1) : "memory");
}
#define CPA16(dst, src) asm volatile("cp.async.cg.shared.global [%0], [%1], 16;" :: "r"(dst), "l"(src) : "memory")
#define CPC()  asm volatile("cp.async.commit_group;" ::: "memory")
#define CPW2() asm volatile("cp.async.wait_group 2;" ::: "memory")
#define CPW1() asm volatile("cp.async.wait_group 1;" ::: "memory")
#define CPW0() asm volatile("cp.async.wait_group 0;" ::: "memory")

// ---------------- kernel: fused weight-cast + gate-table precompute --------
// blocks [0, NW4/256): cast W1+W2 fp32->fp16 (float4 granularity)
// blocks [NW4/256, +64): per-(b,e) gate table + constant + zero counts
#define NW4 (En * Dn * Hn / 4)
__global__ __launch_bounds__(256) void init_kernel(const float* __restrict__ W1,
                                                   const float* __restrict__ W2,
                                                   __half* __restrict__ o1,
                                                   __half* __restrict__ o2,
                                                   const float* __restrict__ log_sigmas,
                                                   const float* __restrict__ mus) {
    int tid = threadIdx.x;
    if (blockIdx.x < NW4 / 256) {
        int i = blockIdx.x * 256 + tid;
        float4 a = ((const float4*)W1)[i];
        float4 b = ((const float4*)W2)[i];
        __half2 a0 = __floats2half2_rn(a.x, a.y), a1 = __floats2half2_rn(a.z, a.w);
        __half2 b0 = __floats2half2_rn(b.x, b.y), b1 = __floats2half2_rn(b.z, b.w);
        uint2 pa, pb;
        pa.x = *(uint32_t*)&a0; pa.y = *(uint32_t*)&a1;
        pb.x = *(uint32_t*)&b0; pb.y = *(uint32_t*)&b1;
        ((uint2*)o1)[i] = pa;
        ((uint2*)o2)[i] = pb;
        return;
    }
    int be = blockIdx.x - NW4 / 256;      // 0..63
    if (be == 0 && tid < En) g_counts[tid] = 0;
    __shared__ float red[256];
    float s = 0.0f;
    for (int d = tid; d < Dn; d += 256) {
        float ls = log_sigmas[be * Dn + d];
        float mu = mus[be * Dn + d];
        float s2 = __expf(-2.0f * ls);
        g_tab[be * Dn + d] = make_float2(s2, mu * s2);
        s += -0.5f * mu * mu * s2 - ls;
    }
    red[tid] = s;
    __syncthreads();
    for (int o = 128; o > 0; o >>= 1) {
        if (tid < o) red[tid] += red[tid + o];
        __syncthreads();
    }
    if (tid == 0) g_C[be] = red[0] - 0.5f * LOG_2PI * (float)Dn;
}

// ---------------- kernel: gating + fused x->fp16 cast ----------------------
__global__ __launch_bounds__(256, 3) void gate_kernel(const float* __restrict__ x,
                                                      __half* __restrict__ xh,
                                                      float* __restrict__ out_lp,
                                                      float* __restrict__ out_ti,
                                                      int has_lp, int has_ti) {
    __shared__ __align__(16) float2 stab[En * Dn];   // 32 KB
    int tid = threadIdx.x;
    int warp = tid >> 5, lane = tid & 31;
    int b = blockIdx.x >> 6;           // 64 CTAs per batch

    {   // coalesced float4 table fill
        const float4* src = (const float4*)(g_tab + b * En * Dn);
        float4* dst = (float4*)stab;
        for (int i = tid; i < En * Dn / 2; i += 256) dst[i] = src[i];
    }
    __syncthreads();

    int t0 = blockIdx.x * 16 + warp * 2;
    int t1 = t0 + 1;

    float xr0[16], xr1[16];
#pragma unroll
    for (int i = 0; i < 8; i++) {
        float2 v0 = *(const float2*)(x + (size_t)t0 * Dn + lane * 2 + 64 * i);
        float2 v1 = *(const float2*)(x + (size_t)t1 * Dn + lane * 2 + 64 * i);
        xr0[2 * i] = v0.x; xr0[2 * i + 1] = v0.y;
        xr1[2 * i] = v1.x; xr1[2 * i + 1] = v1.y;
    }
#pragma unroll
    for (int i = 0; i < 8; i++) {
        __half2 h0 = __floats2half2_rn(xr0[2 * i], xr0[2 * i + 1]);
        __half2 h1 = __floats2half2_rn(xr1[2 * i], xr1[2 * i + 1]);
        *(uint32_t*)(xh + (size_t)t0 * Dn + lane * 2 + 64 * i) = *(uint32_t*)&h0;
        *(uint32_t*)(xh + (size_t)t1 * Dn + lane * 2 + 64 * i) = *(uint32_t*)&h1;
    }

    float s0[En], s1[En];
#pragma unroll
    for (int e = 0; e < En; e++) {
        const float4* tb = (const float4*)(stab + e * Dn);
        float a10 = 0.0f, a20 = 0.0f, a11 = 0.0f, a21 = 0.0f;
#pragma unroll
        for (int i = 0; i < 8; i++) {
            float4 p = tb[lane + 32 * i];
            a10 = fmaf(xr0[2 * i] * p.x, xr0[2 * i], a10);
            a20 = fmaf(xr0[2 * i], p.y, a20);
            a10 = fmaf(xr0[2 * i + 1] * p.z, xr0[2 * i + 1], a10);
            a20 = fmaf(xr0[2 * i + 1], p.w, a20);
            a11 = fmaf(xr1[2 * i] * p.x, xr1[2 * i], a11);
            a21 = fmaf(xr1[2 * i], p.y, a21);
            a11 = fmaf(xr1[2 * i + 1] * p.z, xr1[2 * i + 1], a11);
            a21 = fmaf(xr1[2 * i + 1], p.w, a21);
        }
        s0[e] = a20 - 0.5f * a10;
        s1[e] = a21 - 0.5f * a11;
    }
#pragma unroll
    for (int o = 16; o > 0; o >>= 1) {
#pragma unroll
        for (int e = 0; e < En; e++) {
            s0[e] += __shfl_xor_sync(0xffffffffu, s0[e], o);
            s1[e] += __shfl_xor_sync(0xffffffffu, s1[e], o);
        }
    }

    if (lane < 2) {
        int t = (lane == 0) ? t0 : t1;
        float lp[En];
#pragma unroll
        for (int e = 0; e < En; e++)
            lp[e] = ((lane == 0) ? s0[e] : s1[e]) + g_C[b * En + e];
        int e0 = 0;
#pragma unroll
        for (int e = 1; e < En; e++) if (lp[e] > lp[e0]) e0 = e;
        int e1 = -1;
#pragma unroll
        for (int e = 0; e < En; e++) {
            if (e == e0) continue;
            if (e1 < 0 || lp[e] > lp[e1]) e1 = e;
        }
        float p1 = __expf(lp[e1] - lp[e0]);
        float inv = 1.0f / (1.0f + p1);
        g_gate[t * 2 + 0] = inv;
        g_gate[t * 2 + 1] = p1 * inv;
        int p = atomicAdd(&g_counts[e0], 1);
        g_list[e0][p] = (t << 1) | 0;
        p = atomicAdd(&g_counts[e1], 1);
        g_list[e1][p] = (t << 1) | 1;
        if (has_lp) {
#pragma unroll
            for (int e = 0; e < En; e++) out_lp[t * En + e] = lp[e];
        }
        if (has_ti) {
            out_ti[t * 2 + 0] = (float)e0;
            out_ti[t * 2 + 1] = (float)e1;
        }
    }
}

// ---------------- warp-MMA grouped GEMM, 4-stage, sw-pipelined frags -------
// CTA 128x128, 8 warps (warp tile 32x64), K-step 32. fp16 A (m-major),
// B k-major via ldmatrix.trans.
// MODE 0: h = gelu(xh @ W1 + b1) -> g_hh fp16. K=512, N=1024, A row = en>>1.
// MODE 1: y[t] += gate*(g_hh @ W2 + b2) via red.v2. K=1024, N=512, A row = en.
#define ROWB_A 80
#define ROWB_B 272
#define STG_A (128 * ROWB_A)           // 10240
#define STG_B (32 * ROWB_B)            // 8704
#define STG_BYTES (STG_A + STG_B)      // 18944
#define NSTG 4
template <int MODE>
__global__ __launch_bounds__(256, 2) void gemm_mma(const __half* __restrict__ Aglob,
                                                   const __half* __restrict__ Bg,
                                                   const float* __restrict__ bias,
                                                   float* __restrict__ outf,
                                                   __half* __restrict__ outh) {
    constexpr int Ktot = MODE ? Hn : Dn;
    constexpr int Ntot = MODE ? Dn : Hn;
    constexpr int NCH = Ktot / 32;

    int e = blockIdx.z;
    int cnt = g_counts[e];
    int row0 = blockIdx.y * 128;
    if (row0 >= cnt) return;
    int n0 = blockIdx.x * 128;

    extern __shared__ char sdyn[];
    __shared__ int ent[128];
    __shared__ int rowIdx[128];
    __shared__ float gw[128];

    int tid = threadIdx.x, lane = tid & 31, wid = tid >> 5;
    int warp_m = wid & 3, warp_n = wid >> 2;

    if (tid < 128) {
        int en = (row0 + tid < cnt) ? g_list[e][row0 + tid] : -1;
        ent[tid] = en;
        gw[tid] = (en >= 0) ? g_gate[en] : 0.0f;
        int safe = g_list[e][row0];
        int use = (en >= 0) ? en : safe;
        rowIdx[tid] = MODE ? use : (use >> 1);
    }
    __syncthreads();

    const __half* Be = Bg + (size_t)e * Ktot * Ntot + n0;
    uint32_t sbase = smem_u32(sdyn);

    // hoisted per-thread prefetch pointers (loop-invariant rows)
    int am0 = tid >> 2, ac0 = tid & 3;          // A chunk 0: row am0
    int am1 = (tid + 256) >> 2;                 // A chunk 1
    const __half* aSrc0 = Aglob + (size_t)rowIdx[am0] * Ktot + ac0 * 8;
    const __half* aSrc1 = Aglob + (size_t)rowIdx[am1] * Ktot + ac0 * 8;
    uint32_t aDst0 = am0 * ROWB_A + ac0 * 16;
    uint32_t aDst1 = am1 * ROWB_A + ac0 * 16;
    int br0 = tid >> 4, bc0 = tid & 15;         // B chunk 0: k-row br0
    int br1 = (tid + 256) >> 4;
    const __half* bSrc0 = Be + (size_t)br0 * Ntot + bc0 * 8;
    const __half* bSrc1 = Be + (size_t)br1 * Ntot + bc0 * 8;
    uint32_t bDst0 = STG_A + br0 * ROWB_B + bc0 * 16;
    uint32_t bDst1 = STG_A + br1 * ROWB_B + bc0 * 16;

    float c[2][8][4];
#pragma unroll
    for (int i = 0; i < 2; i++)
#pragma unroll
        for (int j = 0; j < 8; j++)
#pragma unroll
            for (int q = 0; q < 4; q++) c[i][j][q] = 0.0f;

    uint32_t a_row = (uint32_t)(lane & 15);
    uint32_t a_kh  = (uint32_t)((lane >> 4) << 3);
    uint32_t b_krow = (uint32_t)((lane & 7) + (lane & 8));
    uint32_t b_ncol = (uint32_t)((lane >> 4) << 3);
    // hoisted ldsm offsets
    uint32_t aOff0 = (uint32_t)(warp_m * 32 + a_row) * ROWB_A + a_kh * 2;
    uint32_t aOff1 = aOff0 + 16 * ROWB_A;
    uint32_t bColB = (uint32_t)(warp_n * 64 + b_ncol) * 2;

    auto prefetch = [&](int k0, int s) {
        uint32_t base = sbase + s * STG_BYTES;
        const __half* a0 = aSrc0 + k0;
        const __half* a1 = aSrc1 + k0;
        CPA16(base + aDst0, a0);
        CPA16(base + aDst1, a1);
        const __half* b0 = bSrc0 + (size_t)k0 * Ntot;
        const __half* b1 = bSrc1 + (size_t)k0 * Ntot;
        CPA16(base + bDst0, b0);
        CPA16(base + bDst1, b1);
    };

    prefetch(0, 0);
    CPC();
    prefetch(32, 1);
    CPC();

    for (int cc = 0; cc < NCH; cc++) {
        int s = cc % NSTG;
        if (cc + 2 < NCH) {
            prefetch((cc + 2) * 32, (cc + 2) % NSTG);
            CPC();
            CPW2();
        } else if (cc + 1 < NCH) {
            CPW1();
        } else {
            CPW0();
        }
        __syncthreads();   // single barrier: NSTG=4 protects stage reuse

        uint32_t baseA = sbase + s * STG_BYTES;
        uint32_t baseB = baseA + STG_A;

        // ---- software-pipelined fragment schedule ----
        uint32_t ah0[2][4], ah1[2][4];          // A frags for kk=0,1
        ldsm4(ah0[0], baseA + aOff0);
        ldsm4(ah0[1], baseA + aOff1);
        ldsm4(ah1[0], baseA + aOff0 + 16 * 2);  // kk=1: +16 halfs in k
        ldsm4(ah1[1], baseA + aOff1 + 16 * 2);

        uint32_t bh[8][2];
        {   // kk=0 B frags
            uint32_t kb = b_krow * ROWB_B + bColB;
#pragma unroll
            for (int p = 0; p < 4; p++) {
                uint32_t r4[4];
                ldsm4t(r4, baseB + kb + (uint32_t)(p * 16) * 2);
                bh[2 * p][0] = r4[0]; bh[2 * p][1] = r4[1];
                bh[2 * p + 1][0] = r4[2]; bh[2 * p + 1][1] = r4[3];
            }
        }
#pragma unroll
        for (int mt = 0; mt < 2; mt++)
#pragma unroll
            for (int nt = 0; nt < 8; nt++)
                mma16816(c[mt][nt], ah0[mt], bh[nt]);

        {   // kk=1 B frags (overlap with kk=0 mmas via scheduler)
            uint32_t kb = (16 + b_krow) * ROWB_B + bColB;
#pragma unroll
            for (int p = 0; p < 4; p++) {
                uint32_t r4[4];
                ldsm4t(r4, baseB + kb + (uint32_t)(p * 16) * 2);
                bh[2 * p][0] = r4[0]; bh[2 * p][1] = r4[1];
                bh[2 * p + 1][0] = r4[2]; bh[2 * p + 1][1] = r4[3];
            }
        }
#pragma unroll
        for (int mt = 0; mt < 2; mt++)
#pragma unroll
            for (int nt = 0; nt < 8; nt++)
                mma16816(c[mt][nt], ah1[mt], bh[nt]);
    }

    __syncthreads();

    // ---- epilogue ----
#pragma unroll
    for (int mt = 0; mt < 2; mt++) {
#pragma unroll
        for (int nt = 0; nt < 8; nt++) {
            int col = n0 + warp_n * 64 + nt * 8 + (lane & 3) * 2;
#pragma unroll
            for (int half = 0; half < 2; half++) {
                int m = warp_m * 32 + mt * 16 + (lane >> 2) + half * 8;
                int en = ent[m];
                if (en < 0) continue;
                float v0 = c[mt][nt][half * 2 + 0] + bias[e * Ntot + col];
                float v1 = c[mt][nt][half * 2 + 1] + bias[e * Ntot + col + 1];
                if (MODE == 0) {
                    float ga = 0.5f * v0 * (1.0f + erff(v0 * 0.7071067811865476f));
                    float gb = 0.5f * v1 * (1.0f + erff(v1 * 0.7071067811865476f));
                    __half2 h2 = __floats2half2_rn(ga, gb);
                    *(uint32_t*)(outh + (size_t)en * Hn + col) = *(uint32_t*)&h2;
                } else {
                    float g = gw[m];
                    int t = en >> 1;
                    red2(outf + (size_t)t * Dn + col, v0 * g, v1 * g);
                }
            }
        }
    }
}

// ---------------- launch ----------------------------------------------------
extern "C" void kernel_launch(void* const* d_in, const int* in_sizes, int n_in,
                              void* d_out, int out_size) {
    const float* x   = (const float*)d_in[0];
    const float* mus = (const float*)d_in[1];
    const float* ls  = (const float*)d_in[2];
    const float* W1  = (const float*)d_in[3];
    const float* b1  = (const float*)d_in[4];
    const float* W2  = (const float*)d_in[5];
    const float* b2  = (const float*)d_in[6];
    float* out = (float*)d_out;

    const int Ny  = Nn * Dn;
    const int Nlp = Nn * En;
    const int Nti = Nn * Kn;
    int has_lp = (out_size >= Ny + Nlp) ? 1 : 0;
    int has_ti = (out_size >= Ny + Nlp + Nti) ? 1 : 0;
    float* out_lp = out + Ny;
    float* out_ti = out + Ny + Nlp;

    cudaFuncSetAttribute(gemm_mma<0>, cudaFuncAttributeMaxDynamicSharedMemorySize, NSTG * STG_BYTES);
    cudaFuncSetAttribute(gemm_mma<1>, cudaFuncAttributeMaxDynamicSharedMemorySize, NSTG * STG_BYTES);

    // zero the y region (gemm2 accumulates into it via red.v2)
    cudaMemsetAsync(out, 0, (size_t)Ny * sizeof(float));

    __half *w1, *w2, *hh, *xh;
    cudaGetSymbolAddress((void**)&w1, g_w1);
    cudaGetSymbolAddress((void**)&w2, g_w2);
    cudaGetSymbolAddress((void**)&hh, g_hh);
    cudaGetSymbolAddress((void**)&xh, g_xh);

    init_kernel<<<NW4 / 256 + Bn * En, 256>>>(W1, W2, w1, w2, ls, mus);

    gate_kernel<<<Nn / 16, 256>>>(x, xh, out_lp, out_ti, has_lp, has_ti);

    dim3 g1(Hn / 128, Nn / 128, En);
    gemm_mma<0><<<g1, 256, NSTG * STG_BYTES>>>(xh, w1, b1, nullptr, hh);

    dim3 g2(Dn / 128, Nn / 128, En);
    gemm_mma<1><<<g2, 256, NSTG * STG_BYTES>>>(hh, w2, b2, out, nullptr);

    (void)in_sizes; (void)n_in;
}

// round 14
// speedup vs baseline: 1.7563x; 1.0116x over previous
#include <cuda_runtime.h>
#include <cuda_fp16.h>
#include <math.h>
#include <stdint.h>

// Problem dims
#define Bn 8
#define Tn 1024
#define Dn 512
#define Hn 1024
#define En 8
#define Kn 2
#define Nn (Bn * Tn)          // 8192 tokens
#define LOG_2PI 1.8378770664093453f

// ---------------- scratch (static __device__ globals) ----------------------
__device__ __half g_hh[(size_t)Nn * Kn * Hn];          // gelu(h) fp16, [slot][H]
__device__ __half g_xh[(size_t)Nn * Dn];               // x cast to fp16
__device__ float  g_gate[Nn * Kn];
__device__ int    g_counts[En];
__device__ int    g_list[En][Nn];
__device__ __align__(16) float2 g_tab[Bn * En * Dn];   // (isig2, mu*isig2)
__device__ float  g_C[Bn * En];                        // per-(b,e) constant
__device__ __half g_w1[(size_t)En * Dn * Hn];          // W1 [E][D][H] fp16 (k-major)
__device__ __half g_w2[(size_t)En * Hn * Dn];          // W2 [E][H][D] fp16 (k-major)

// ---------------- helpers ---------------------------------------------------
__device__ __forceinline__ uint32_t smem_u32(const void* p) {
    uint32_t a;
    asm("{ .reg .u64 t; cvta.to.shared.u64 t, %1; cvt.u32.u64 %0, t; }" : "=r"(a) : "l"(p));
    return a;
}
__device__ __forceinline__ void ldsm4(uint32_t* r, uint32_t addr) {
    asm volatile("ldmatrix.sync.aligned.m8n8.x4.shared.b16 {%0,%1,%2,%3}, [%4];"
        : "=r"(r[0]), "=r"(r[1]), "=r"(r[2]), "=r"(r[3]) : "r"(addr));
}
__device__ __forceinline__ void ldsm4t(uint32_t* r, uint32_t addr) {
    asm volatile("ldmatrix.sync.aligned.m8n8.x4.trans.shared.b16 {%0,%1,%2,%3}, [%4];"
        : "=r"(r[0]), "=r"(r[1]), "=r"(r[2]), "=r"(r[3]) : "r"(addr));
}
__device__ __forceinline__ void mma16816(float* c, const uint32_t* a, const uint32_t* b) {
    asm volatile("mma.sync.aligned.m16n8k16.row.col.f32.f16.f16.f32 "
        "{%0,%1,%2,%3}, {%4,%5,%6,%7}, {%8,%9}, {%0,%1,%2,%3};"
        : "+f"(c[0]), "+f"(c[1]), "+f"(c[2]), "+f"(c[3])
        : "r"(a[0]), "r"(a[1]), "r"(a[2]), "r"(a[3]), "r"(b[0]), "r"(b[1]));
}
__device__ __forceinline__ void red2(float* ptr, float v0, float v1) {
    asm volatile("red.global.add.v2.f32 [%0], {%1, %2};"
        :: "l"(ptr), "f"(v0), "f"(v1) : "memory");
}
#define CPA16(dst, src) asm volatile("cp.async.cg.shared.global [%0], [%1], 16;" :: "r"(dst), "l"(src) : "memory")
#define CPC()  asm volatile("cp.async.commit_group;" ::: "memory")
#define CPW0() asm volatile("cp.async.wait_group 0;" ::: "memory")

// ---------------- kernel: fused weight-cast + gate-table precompute --------
#define NW4 (En * Dn * Hn / 4)
__global__ __launch_bounds__(256) void init_kernel(const float* __restrict__ W1,
                                                   const float* __restrict__ W2,
                                                   __half* __restrict__ o1,
                                                   __half* __restrict__ o2,
                                                   const float* __restrict__ log_sigmas,
                                                   const float* __restrict__ mus) {
    int tid = threadIdx.x;
    if (blockIdx.x < NW4 / 256) {
        int i = blockIdx.x * 256 + tid;
        float4 a = ((const float4*)W1)[i];
        float4 b = ((const float4*)W2)[i];
        __half2 a0 = __floats2half2_rn(a.x, a.y), a1 = __floats2half2_rn(a.z, a.w);
        __half2 b0 = __floats2half2_rn(b.x, b.y), b1 = __floats2half2_rn(b.z, b.w);
        uint2 pa, pb;
        pa.x = *(uint32_t*)&a0; pa.y = *(uint32_t*)&a1;
        pb.x = *(uint32_t*)&b0; pb.y = *(uint32_t*)&b1;
        ((uint2*)o1)[i] = pa;
        ((uint2*)o2)[i] = pb;
        return;
    }
    int be = blockIdx.x - NW4 / 256;      // 0..63
    if (be == 0 && tid < En) g_counts[tid] = 0;
    __shared__ float red[256];
    float s = 0.0f;
    for (int d = tid; d < Dn; d += 256) {
        float ls = log_sigmas[be * Dn + d];
        float mu = mus[be * Dn + d];
        float s2 = __expf(-2.0f * ls);
        g_tab[be * Dn + d] = make_float2(s2, mu * s2);
        s += -0.5f * mu * mu * s2 - ls;
    }
    red[tid] = s;
    __syncthreads();
    for (int o = 128; o > 0; o >>= 1) {
        if (tid < o) red[tid] += red[tid + o];
        __syncthreads();
    }
    if (tid == 0) g_C[be] = red[0] - 0.5f * LOG_2PI * (float)Dn;
}

// ---------------- kernel: gating + fused x->fp16 cast ----------------------
__global__ __launch_bounds__(256, 3) void gate_kernel(const float* __restrict__ x,
                                                      __half* __restrict__ xh,
                                                      float* __restrict__ out_lp,
                                                      float* __restrict__ out_ti,
                                                      int has_lp, int has_ti) {
    __shared__ __align__(16) float2 stab[En * Dn];   // 32 KB
    int tid = threadIdx.x;
    int warp = tid >> 5, lane = tid & 31;
    int b = blockIdx.x >> 6;           // 64 CTAs per batch

    {
        const float4* src = (const float4*)(g_tab + b * En * Dn);
        float4* dst = (float4*)stab;
        for (int i = tid; i < En * Dn / 2; i += 256) dst[i] = src[i];
    }
    __syncthreads();

    int t0 = blockIdx.x * 16 + warp * 2;
    int t1 = t0 + 1;

    float xr0[16], xr1[16];
#pragma unroll
    for (int i = 0; i < 8; i++) {
        float2 v0 = *(const float2*)(x + (size_t)t0 * Dn + lane * 2 + 64 * i);
        float2 v1 = *(const float2*)(x + (size_t)t1 * Dn + lane * 2 + 64 * i);
        xr0[2 * i] = v0.x; xr0[2 * i + 1] = v0.y;
        xr1[2 * i] = v1.x; xr1[2 * i + 1] = v1.y;
    }
#pragma unroll
    for (int i = 0; i < 8; i++) {
        __half2 h0 = __floats2half2_rn(xr0[2 * i], xr0[2 * i + 1]);
        __half2 h1 = __floats2half2_rn(xr1[2 * i], xr1[2 * i + 1]);
        *(uint32_t*)(xh + (size_t)t0 * Dn + lane * 2 + 64 * i) = *(uint32_t*)&h0;
        *(uint32_t*)(xh + (size_t)t1 * Dn + lane * 2 + 64 * i) = *(uint32_t*)&h1;
    }

    float s0[En], s1[En];
#pragma unroll
    for (int e = 0; e < En; e++) {
        const float4* tb = (const float4*)(stab + e * Dn);
        float a10 = 0.0f, a20 = 0.0f, a11 = 0.0f, a21 = 0.0f;
#pragma unroll
        for (int i = 0; i < 8; i++) {
            float4 p = tb[lane + 32 * i];
            a10 = fmaf(xr0[2 * i] * p.x, xr0[2 * i], a10);
            a20 = fmaf(xr0[2 * i], p.y, a20);
            a10 = fmaf(xr0[2 * i + 1] * p.z, xr0[2 * i + 1], a10);
            a20 = fmaf(xr0[2 * i + 1], p.w, a20);
            a11 = fmaf(xr1[2 * i] * p.x, xr1[2 * i], a11);
            a21 = fmaf(xr1[2 * i], p.y, a21);
            a11 = fmaf(xr1[2 * i + 1] * p.z, xr1[2 * i + 1], a11);
            a21 = fmaf(xr1[2 * i + 1], p.w, a21);
        }
        s0[e] = a20 - 0.5f * a10;
        s1[e] = a21 - 0.5f * a11;
    }
#pragma unroll
    for (int o = 16; o > 0; o >>= 1) {
#pragma unroll
        for (int e = 0; e < En; e++) {
            s0[e] += __shfl_xor_sync(0xffffffffu, s0[e], o);
            s1[e] += __shfl_xor_sync(0xffffffffu, s1[e], o);
        }
    }

    if (lane < 2) {
        int t = (lane == 0) ? t0 : t1;
        float lp[En];
#pragma unroll
        for (int e = 0; e < En; e++)
            lp[e] = ((lane == 0) ? s0[e] : s1[e]) + g_C[b * En + e];
        int e0 = 0;
#pragma unroll
        for (int e = 1; e < En; e++) if (lp[e] > lp[e0]) e0 = e;
        int e1 = -1;
#pragma unroll
        for (int e = 0; e < En; e++) {
            if (e == e0) continue;
            if (e1 < 0 || lp[e] > lp[e1]) e1 = e;
        }
        float p1 = __expf(lp[e1] - lp[e0]);
        float inv = 1.0f / (1.0f + p1);
        g_gate[t * 2 + 0] = inv;
        g_gate[t * 2 + 1] = p1 * inv;
        int p = atomicAdd(&g_counts[e0], 1);
        g_list[e0][p] = (t << 1) | 0;
        p = atomicAdd(&g_counts[e1], 1);
        g_list[e1][p] = (t << 1) | 1;
        if (has_lp) {
#pragma unroll
            for (int e = 0; e < En; e++) out_lp[t * En + e] = lp[e];
        }
        if (has_ti) {
            out_ti[t * 2 + 0] = (float)e0;
            out_ti[t * 2 + 1] = (float)e1;
        }
    }
}

// ---------------- warp-MMA grouped GEMM, K-chunk 64, double-buffered -------
// CTA 128x128, 8 warps (warp tile 32x64). fp16 A (m-major), B k-major via
// ldmatrix.trans. Half the barriers of the 32-chunk version.
// MODE 0: h = gelu(xh @ W1 + b1) -> g_hh fp16. K=512, N=1024, A row = en>>1.
// MODE 1: y[t] += gate*(g_hh @ W2 + b2) via red.v2. K=1024, N=512, A row = en.
#define ROWB_A 144                     // 64 k-halfs * 2B + 16 pad
#define ROWB_B 272                     // 128 n * 2B + 16 pad
#define STG_A (128 * ROWB_A)           // 18432
#define STG_B (64 * ROWB_B)            // 17408
#define STG_BYTES (STG_A + STG_B)      // 35840
#define NSTG 2
template <int MODE>
__global__ __launch_bounds__(256, 2) void gemm_mma(const __half* __restrict__ Aglob,
                                                   const __half* __restrict__ Bg,
                                                   const float* __restrict__ bias,
                                                   float* __restrict__ outf,
                                                   __half* __restrict__ outh) {
    constexpr int Ktot = MODE ? Hn : Dn;
    constexpr int Ntot = MODE ? Dn : Hn;
    constexpr int NCH = Ktot / 64;

    int e = blockIdx.z;
    int cnt = g_counts[e];
    int row0 = blockIdx.y * 128;
    if (row0 >= cnt) return;
    int n0 = blockIdx.x * 128;

    extern __shared__ char sdyn[];
    __shared__ int ent[128];
    __shared__ int rowIdx[128];
    __shared__ float gw[128];

    int tid = threadIdx.x, lane = tid & 31, wid = tid >> 5;
    int warp_m = wid & 3, warp_n = wid >> 2;

    if (tid < 128) {
        int en = (row0 + tid < cnt) ? g_list[e][row0 + tid] : -1;
        ent[tid] = en;
        gw[tid] = (en >= 0) ? g_gate[en] : 0.0f;
        int safe = g_list[e][row0];
        int use = (en >= 0) ? en : safe;
        rowIdx[tid] = MODE ? use : (use >> 1);
    }
    __syncthreads();

    const __half* Be = Bg + (size_t)e * Ktot * Ntot + n0;
    uint32_t sbase = smem_u32(sdyn);

    // hoisted per-thread prefetch pointers
    int amr = tid >> 3, ac8 = tid & 7;          // A: 4 rows/thread, fixed col chunk
    const __half* aS[4];
    uint32_t aD[4];
#pragma unroll
    for (int j = 0; j < 4; j++) {
        int m = amr + 32 * j;
        aS[j] = Aglob + (size_t)rowIdx[m] * Ktot + ac8 * 8;
        aD[j] = (uint32_t)(m * ROWB_A + ac8 * 16);
    }
    int brr = tid >> 4, bc8 = tid & 15;         // B: 4 k-rows/thread
    const __half* bS = Be + (size_t)brr * Ntot + bc8 * 8;
    uint32_t bD = (uint32_t)(STG_A + brr * ROWB_B + bc8 * 16);

    float c[2][8][4];
#pragma unroll
    for (int i = 0; i < 2; i++)
#pragma unroll
        for (int j = 0; j < 8; j++)
#pragma unroll
            for (int q = 0; q < 4; q++) c[i][j][q] = 0.0f;

    uint32_t a_row = (uint32_t)(lane & 15);
    uint32_t a_kh  = (uint32_t)((lane >> 4) << 3);
    uint32_t b_krow = (uint32_t)((lane & 7) + (lane & 8));
    uint32_t b_ncol = (uint32_t)((lane >> 4) << 3);
    uint32_t aOff0 = (uint32_t)(warp_m * 32 + a_row) * ROWB_A + a_kh * 2;
    uint32_t aOff1 = aOff0 + 16 * ROWB_A;
    uint32_t bColB = (uint32_t)(warp_n * 64 + b_ncol) * 2;

    auto prefetch = [&](int k0, int s) {
        uint32_t base = sbase + s * STG_BYTES;
#pragma unroll
        for (int j = 0; j < 4; j++) CPA16(base + aD[j], aS[j] + k0);
        const __half* bp = bS + (size_t)k0 * Ntot;
#pragma unroll
        for (int j = 0; j < 4; j++)
            CPA16(base + bD + (uint32_t)(j * 16 * ROWB_B), bp + (size_t)(j * 16) * Ntot);
    };

    prefetch(0, 0);
    CPC();

    for (int cc = 0; cc < NCH; cc++) {
        int s = cc & 1;
        CPW0();                 // chunk cc landed (only its group pending)
        __syncthreads();        // all warps done with chunk cc-1 (stage s^1)
        if (cc + 1 < NCH) {
            prefetch((cc + 1) * 64, s ^ 1);   // overlaps compute below
            CPC();
        }

        uint32_t baseA = sbase + s * STG_BYTES;
        uint32_t baseB = baseA + STG_A;
#pragma unroll
        for (int kk = 0; kk < 4; kk++) {
            uint32_t ah[2][4];
            ldsm4(ah[0], baseA + aOff0 + kk * 32);
            ldsm4(ah[1], baseA + aOff1 + kk * 32);
            uint32_t bh[8][2];
            uint32_t kb = (uint32_t)(kk * 16 + b_krow) * ROWB_B + bColB;
#pragma unroll
            for (int p = 0; p < 4; p++) {
                uint32_t r4[4];
                ldsm4t(r4, baseB + kb + (uint32_t)(p * 16) * 2);
                bh[2 * p][0] = r4[0]; bh[2 * p][1] = r4[1];
                bh[2 * p + 1][0] = r4[2]; bh[2 * p + 1][1] = r4[3];
            }
#pragma unroll
            for (int mt = 0; mt < 2; mt++)
#pragma unroll
                for (int nt = 0; nt < 8; nt++)
                    mma16816(c[mt][nt], ah[mt], bh[nt]);
        }
    }

    // ---- epilogue (no barrier needed: reads only regs + pre-loop smem) ----
#pragma unroll
    for (int mt = 0; mt < 2; mt++) {
#pragma unroll
        for (int nt = 0; nt < 8; nt++) {
            int col = n0 + warp_n * 64 + nt * 8 + (lane & 3) * 2;
#pragma unroll
            for (int half = 0; half < 2; half++) {
                int m = warp_m * 32 + mt * 16 + (lane >> 2) + half * 8;
                int en = ent[m];
                if (en < 0) continue;
                float v0 = c[mt][nt][half * 2 + 0] + bias[e * Ntot + col];
                float v1 = c[mt][nt][half * 2 + 1] + bias[e * Ntot + col + 1];
                if (MODE == 0) {
                    float ga = 0.5f * v0 * (1.0f + erff(v0 * 0.7071067811865476f));
                    float gb = 0.5f * v1 * (1.0f + erff(v1 * 0.7071067811865476f));
                    __half2 h2 = __floats2half2_rn(ga, gb);
                    *(uint32_t*)(outh + (size_t)en * Hn + col) = *(uint32_t*)&h2;
                } else {
                    float g = gw[m];
                    int t = en >> 1;
                    red2(outf + (size_t)t * Dn + col, v0 * g, v1 * g);
                }
            }
        }
    }
}

// ---------------- launch ----------------------------------------------------
extern "C" void kernel_launch(void* const* d_in, const int* in_sizes, int n_in,
                              void* d_out, int out_size) {
    const float* x   = (const float*)d_in[0];
    const float* mus = (const float*)d_in[1];
    const float* ls  = (const float*)d_in[2];
    const float* W1  = (const float*)d_in[3];
    const float* b1  = (const float*)d_in[4];
    const float* W2  = (const float*)d_in[5];
    const float* b2  = (const float*)d_in[6];
    float* out = (float*)d_out;

    const int Ny  = Nn * Dn;
    const int Nlp = Nn * En;
    const int Nti = Nn * Kn;
    int has_lp = (out_size >= Ny + Nlp) ? 1 : 0;
    int has_ti = (out_size >= Ny + Nlp + Nti) ? 1 : 0;
    float* out_lp = out + Ny;
    float* out_ti = out + Ny + Nlp;

    cudaFuncSetAttribute(gemm_mma<0>, cudaFuncAttributeMaxDynamicSharedMemorySize, NSTG * STG_BYTES);
    cudaFuncSetAttribute(gemm_mma<1>, cudaFuncAttributeMaxDynamicSharedMemorySize, NSTG * STG_BYTES);

    // zero the y region (gemm2 accumulates into it via red.v2)
    cudaMemsetAsync(out, 0, (size_t)Ny * sizeof(float));

    __half *w1, *w2, *hh, *xh;
    cudaGetSymbolAddress((void**)&w1, g_w1);
    cudaGetSymbolAddress((void**)&w2, g_w2);
    cudaGetSymbolAddress((void**)&hh, g_hh);
    cudaGetSymbolAddress((void**)&xh, g_xh);

    init_kernel<<<NW4 / 256 + Bn * En, 256>>>(W1, W2, w1, w2, ls, mus);

    gate_kernel<<<Nn / 16, 256>>>(x, xh, out_lp, out_ti, has_lp, has_ti);

    dim3 g1(Hn / 128, Nn / 128, En);
    gemm_mma<0><<<g1, 256, NSTG * STG_BYTES>>>(xh, w1, b1, nullptr, hh);

    dim3 g2(Dn / 128, Nn / 128, En);
    gemm_mma<1><<<g2, 256, NSTG * STG_BYTES>>>(hh, w2, b2, out, nullptr);

    (void)in_sizes; (void)n_in;
}

// round 15
// speedup vs baseline: 1.8969x; 1.0801x over previous
#include <cuda_runtime.h>
#include <cuda_fp16.h>
#include <math.h>
#include <stdint.h>

// Problem dims
#define Bn 8
#define Tn 1024
#define Dn 512
#define Hn 1024
#define En 8
#define Kn 2
#define Nn (Bn * Tn)          // 8192 tokens
#define LOG_2PI 1.8378770664093453f

// ---------------- scratch (static __device__ globals) ----------------------
__device__ __half g_hh[(size_t)Nn * Kn * Hn];          // gelu(h) fp16, [slot][H]
__device__ __half g_xh[(size_t)Nn * Dn];               // x cast to fp16
__device__ float  g_gate[Nn * Kn];
__device__ int    g_counts[En];
__device__ int    g_list[En][Nn];
__device__ int    g_done[En * 64];                     // gemm1 tile completion
__device__ __align__(16) float2 g_tab[Bn * En * Dn];   // (isig2, mu*isig2)
__device__ float  g_C[Bn * En];                        // per-(b,e) constant
__device__ __half g_w1[(size_t)En * Dn * Hn];          // W1 [E][D][H] fp16 (k-major)
__device__ __half g_w2[(size_t)En * Hn * Dn];          // W2 [E][H][D] fp16 (k-major)

// ---------------- helpers ---------------------------------------------------
__device__ __forceinline__ uint32_t smem_u32(const void* p) {
    uint32_t a;
    asm("{ .reg .u64 t; cvta.to.shared.u64 t, %1; cvt.u32.u64 %0, t; }" : "=r"(a) : "l"(p));
    return a;
}
__device__ __forceinline__ void ldsm4(uint32_t* r, uint32_t addr) {
    asm volatile("ldmatrix.sync.aligned.m8n8.x4.shared.b16 {%0,%1,%2,%3}, [%4];"
        : "=r"(r[0]), "=r"(r[1]), "=r"(r[2]), "=r"(r[3]) : "r"(addr));
}
__device__ __forceinline__ void ldsm4t(uint32_t* r, uint32_t addr) {
    asm volatile("ldmatrix.sync.aligned.m8n8.x4.trans.shared.b16 {%0,%1,%2,%3}, [%4];"
        : "=r"(r[0]), "=r"(r[1]), "=r"(r[2]), "=r"(r[3]) : "r"(addr));
}
__device__ __forceinline__ void mma16816(float* c, const uint32_t* a, const uint32_t* b) {
    asm volatile("mma.sync.aligned.m16n8k16.row.col.f32.f16.f16.f32 "
        "{%0,%1,%2,%3}, {%4,%5,%6,%7}, {%8,%9}, {%0,%1,%2,%3};"
        : "+f"(c[0]), "+f"(c[1]), "+f"(c[2]), "+f"(c[3])
        : "r"(a[0]), "r"(a[1]), "r"(a[2]), "r"(a[3]), "r"(b[0]), "r"(b[1]));
}
__device__ __forceinline__ void red2(float* ptr, float v0, float v1) {
    asm volatile("red.global.add.v2.f32 [%0], {%1, %2};"
        :: "l"(ptr), "f"(v0), "f"(v1) : "memory");
}
#define CPA16(dst, src) asm volatile("cp.async.cg.shared.global [%0], [%1], 16;" :: "r"(dst), "l"(src) : "memory")
#define CPC()  asm volatile("cp.async.commit_group;" ::: "memory")
#define CPW0() asm volatile("cp.async.wait_group 0;" ::: "memory")

// ---------------- kernel: fused weight-cast + gate-table precompute --------
#define NW4 (En * Dn * Hn / 4)
__global__ __launch_bounds__(256) void init_kernel(const float* __restrict__ W1,
                                                   const float* __restrict__ W2,
                                                   __half* __restrict__ o1,
                                                   __half* __restrict__ o2,
                                                   const float* __restrict__ log_sigmas,
                                                   const float* __restrict__ mus) {
    int tid = threadIdx.x;
    if (blockIdx.x < NW4 / 256) {
        int i = blockIdx.x * 256 + tid;
        float4 a = ((const float4*)W1)[i];
        float4 b = ((const float4*)W2)[i];
        __half2 a0 = __floats2half2_rn(a.x, a.y), a1 = __floats2half2_rn(a.z, a.w);
        __half2 b0 = __floats2half2_rn(b.x, b.y), b1 = __floats2half2_rn(b.z, b.w);
        uint2 pa, pb;
        pa.x = *(uint32_t*)&a0; pa.y = *(uint32_t*)&a1;
        pb.x = *(uint32_t*)&b0; pb.y = *(uint32_t*)&b1;
        ((uint2*)o1)[i] = pa;
        ((uint2*)o2)[i] = pb;
        return;
    }
    int be = blockIdx.x - NW4 / 256;      // 0..63
    if (be == 0 && tid < En) g_counts[tid] = 0;
    if (tid < 8) g_done[be * 8 + tid] = 0;
    __shared__ float red[256];
    float s = 0.0f;
    for (int d = tid; d < Dn; d += 256) {
        float ls = log_sigmas[be * Dn + d];
        float mu = mus[be * Dn + d];
        float s2 = __expf(-2.0f * ls);
        g_tab[be * Dn + d] = make_float2(s2, mu * s2);
        s += -0.5f * mu * mu * s2 - ls;
    }
    red[tid] = s;
    __syncthreads();
    for (int o = 128; o > 0; o >>= 1) {
        if (tid < o) red[tid] += red[tid + o];
        __syncthreads();
    }
    if (tid == 0) g_C[be] = red[0] - 0.5f * LOG_2PI * (float)Dn;
}

// ---------------- kernel: gating + x->fp16 cast + y zeroing ----------------
__global__ __launch_bounds__(256, 3) void gate_kernel(const float* __restrict__ x,
                                                      __half* __restrict__ xh,
                                                      float* __restrict__ y,
                                                      float* __restrict__ out_lp,
                                                      float* __restrict__ out_ti,
                                                      int has_lp, int has_ti) {
    __shared__ __align__(16) float2 stab[En * Dn];   // 32 KB
    int tid = threadIdx.x;
    int warp = tid >> 5, lane = tid & 31;
    int b = blockIdx.x >> 6;           // 64 CTAs per batch

    // zero this CTA's 16-token slice of y (replaces memset launch)
    {
        float4* yz = (float4*)(y + (size_t)blockIdx.x * 16 * Dn);
        float4 z = make_float4(0.f, 0.f, 0.f, 0.f);
#pragma unroll
        for (int i = 0; i < 8; i++) yz[tid + 256 * i] = z;
    }
    {
        const float4* src = (const float4*)(g_tab + b * En * Dn);
        float4* dst = (float4*)stab;
        for (int i = tid; i < En * Dn / 2; i += 256) dst[i] = src[i];
    }
    __syncthreads();

    int t0 = blockIdx.x * 16 + warp * 2;
    int t1 = t0 + 1;

    float xr0[16], xr1[16];
#pragma unroll
    for (int i = 0; i < 8; i++) {
        float2 v0 = *(const float2*)(x + (size_t)t0 * Dn + lane * 2 + 64 * i);
        float2 v1 = *(const float2*)(x + (size_t)t1 * Dn + lane * 2 + 64 * i);
        xr0[2 * i] = v0.x; xr0[2 * i + 1] = v0.y;
        xr1[2 * i] = v1.x; xr1[2 * i + 1] = v1.y;
    }
#pragma unroll
    for (int i = 0; i < 8; i++) {
        __half2 h0 = __floats2half2_rn(xr0[2 * i], xr0[2 * i + 1]);
        __half2 h1 = __floats2half2_rn(xr1[2 * i], xr1[2 * i + 1]);
        *(uint32_t*)(xh + (size_t)t0 * Dn + lane * 2 + 64 * i) = *(uint32_t*)&h0;
        *(uint32_t*)(xh + (size_t)t1 * Dn + lane * 2 + 64 * i) = *(uint32_t*)&h1;
    }

    float s0[En], s1[En];
#pragma unroll
    for (int e = 0; e < En; e++) {
        const float4* tb = (const float4*)(stab + e * Dn);
        float a10 = 0.0f, a20 = 0.0f, a11 = 0.0f, a21 = 0.0f;
#pragma unroll
        for (int i = 0; i < 8; i++) {
            float4 p = tb[lane + 32 * i];
            a10 = fmaf(xr0[2 * i] * p.x, xr0[2 * i], a10);
            a20 = fmaf(xr0[2 * i], p.y, a20);
            a10 = fmaf(xr0[2 * i + 1] * p.z, xr0[2 * i + 1], a10);
            a20 = fmaf(xr0[2 * i + 1], p.w, a20);
            a11 = fmaf(xr1[2 * i] * p.x, xr1[2 * i], a11);
            a21 = fmaf(xr1[2 * i], p.y, a21);
            a11 = fmaf(xr1[2 * i + 1] * p.z, xr1[2 * i + 1], a11);
            a21 = fmaf(xr1[2 * i + 1], p.w, a21);
        }
        s0[e] = a20 - 0.5f * a10;
        s1[e] = a21 - 0.5f * a11;
    }
#pragma unroll
    for (int o = 16; o > 0; o >>= 1) {
#pragma unroll
        for (int e = 0; e < En; e++) {
            s0[e] += __shfl_xor_sync(0xffffffffu, s0[e], o);
            s1[e] += __shfl_xor_sync(0xffffffffu, s1[e], o);
        }
    }

    if (lane < 2) {
        int t = (lane == 0) ? t0 : t1;
        float lp[En];
#pragma unroll
        for (int e = 0; e < En; e++)
            lp[e] = ((lane == 0) ? s0[e] : s1[e]) + g_C[b * En + e];
        int e0 = 0;
#pragma unroll
        for (int e = 1; e < En; e++) if (lp[e] > lp[e0]) e0 = e;
        int e1 = -1;
#pragma unroll
        for (int e = 0; e < En; e++) {
            if (e == e0) continue;
            if (e1 < 0 || lp[e] > lp[e1]) e1 = e;
        }
        float p1 = __expf(lp[e1] - lp[e0]);
        float inv = 1.0f / (1.0f + p1);
        g_gate[t * 2 + 0] = inv;
        g_gate[t * 2 + 1] = p1 * inv;
        int p = atomicAdd(&g_counts[e0], 1);
        g_list[e0][p] = (t << 1) | 0;
        p = atomicAdd(&g_counts[e1], 1);
        g_list[e1][p] = (t << 1) | 1;
        if (has_lp) {
#pragma unroll
            for (int e = 0; e < En; e++) out_lp[t * En + e] = lp[e];
        }
        if (has_ti) {
            out_ti[t * 2 + 0] = (float)e0;
            out_ti[t * 2 + 1] = (float)e1;
        }
    }
}

// ---------------- fused grouped GEMM (gemm1 + dependent gemm2) -------------
// CTA 128x128, 8 warps (warp tile 32x64), K-chunk 64, double-buffered.
// MODE 0: h = gelu(xh @ W1 + b1) -> g_hh fp16; bumps g_done[e][ytile].
// MODE 1: spins on g_done[e][ytile]==8, then y += gate*(g_hh @ W2 + b2).
#define ROWB_A 144
#define ROWB_B 272
#define STG_A (128 * ROWB_A)           // 18432
#define STG_B (64 * ROWB_B)            // 17408
#define STG_BYTES (STG_A + STG_B)      // 35840
#define NSTG 2
#define G1BLKS 4096                    // 8n * 64y * 8e

template <int MODE>
__device__ __forceinline__ void gemm_body(int n0, int row0, int cnt, int e,
                                          const __half* __restrict__ Aglob,
                                          const __half* __restrict__ Bg,
                                          const float* __restrict__ bias,
                                          float* __restrict__ outf,
                                          __half* __restrict__ outh,
                                          char* sdyn, int* ent, int* rowIdx,
                                          float* gw, int* done) {
    constexpr int Ktot = MODE ? Hn : Dn;
    constexpr int Ntot = MODE ? Dn : Hn;
    constexpr int NCH = Ktot / 64;

    int tid = threadIdx.x, lane = tid & 31, wid = tid >> 5;
    int warp_m = wid & 3, warp_n = wid >> 2;

    if (tid < 128) {
        int en = (row0 + tid < cnt) ? g_list[e][row0 + tid] : -1;
        ent[tid] = en;
        gw[tid] = (en >= 0) ? g_gate[en] : 0.0f;
        int safe = g_list[e][row0];
        int use = (en >= 0) ? en : safe;
        rowIdx[tid] = MODE ? use : (use >> 1);
    }
    if (MODE == 1 && tid == 0) {
        volatile int* p = done;
        while (*p != (Hn / 128)) { __nanosleep(32); }
        __threadfence();
    }
    __syncthreads();

    const __half* Be = Bg + (size_t)e * Ktot * Ntot + n0;
    uint32_t sbase = smem_u32(sdyn);

    int amr = tid >> 3, ac8 = tid & 7;
    const __half* aS[4];
    uint32_t aD[4];
#pragma unroll
    for (int j = 0; j < 4; j++) {
        int m = amr + 32 * j;
        aS[j] = Aglob + (size_t)rowIdx[m] * Ktot + ac8 * 8;
        aD[j] = (uint32_t)(m * ROWB_A + ac8 * 16);
    }
    int brr = tid >> 4, bc8 = tid & 15;
    const __half* bS = Be + (size_t)brr * Ntot + bc8 * 8;
    uint32_t bD = (uint32_t)(STG_A + brr * ROWB_B + bc8 * 16);

    float c[2][8][4];
#pragma unroll
    for (int i = 0; i < 2; i++)
#pragma unroll
        for (int j = 0; j < 8; j++)
#pragma unroll
            for (int q = 0; q < 4; q++) c[i][j][q] = 0.0f;

    uint32_t a_row = (uint32_t)(lane & 15);
    uint32_t a_kh  = (uint32_t)((lane >> 4) << 3);
    uint32_t b_krow = (uint32_t)((lane & 7) + (lane & 8));
    uint32_t b_ncol = (uint32_t)((lane >> 4) << 3);
    uint32_t aOff0 = (uint32_t)(warp_m * 32 + a_row) * ROWB_A + a_kh * 2;
    uint32_t aOff1 = aOff0 + 16 * ROWB_A;
    uint32_t bColB = (uint32_t)(warp_n * 64 + b_ncol) * 2;

    auto prefetch = [&](int k0, int s) {
        uint32_t base = sbase + s * STG_BYTES;
#pragma unroll
        for (int j = 0; j < 4; j++) CPA16(base + aD[j], aS[j] + k0);
        const __half* bp = bS + (size_t)k0 * Ntot;
#pragma unroll
        for (int j = 0; j < 4; j++)
            CPA16(base + bD + (uint32_t)(j * 16 * ROWB_B), bp + (size_t)(j * 16) * Ntot);
    };

    prefetch(0, 0);
    CPC();

    for (int cc = 0; cc < NCH; cc++) {
        int s = cc & 1;
        CPW0();
        __syncthreads();
        if (cc + 1 < NCH) {
            prefetch((cc + 1) * 64, s ^ 1);
            CPC();
        }

        uint32_t baseA = sbase + s * STG_BYTES;
        uint32_t baseB = baseA + STG_A;
#pragma unroll
        for (int kk = 0; kk < 4; kk++) {
            uint32_t ah[2][4];
            ldsm4(ah[0], baseA + aOff0 + kk * 32);
            ldsm4(ah[1], baseA + aOff1 + kk * 32);
            uint32_t bh[8][2];
            uint32_t kb = (uint32_t)(kk * 16 + b_krow) * ROWB_B + bColB;
#pragma unroll
            for (int p = 0; p < 4; p++) {
                uint32_t r4[4];
                ldsm4t(r4, baseB + kb + (uint32_t)(p * 16) * 2);
                bh[2 * p][0] = r4[0]; bh[2 * p][1] = r4[1];
                bh[2 * p + 1][0] = r4[2]; bh[2 * p + 1][1] = r4[3];
            }
#pragma unroll
            for (int mt = 0; mt < 2; mt++)
#pragma unroll
                for (int nt = 0; nt < 8; nt++)
                    mma16816(c[mt][nt], ah[mt], bh[nt]);
        }
    }

    // ---- epilogue ----
#pragma unroll
    for (int mt = 0; mt < 2; mt++) {
#pragma unroll
        for (int nt = 0; nt < 8; nt++) {
            int col = n0 + warp_n * 64 + nt * 8 + (lane & 3) * 2;
#pragma unroll
            for (int half = 0; half < 2; half++) {
                int m = warp_m * 32 + mt * 16 + (lane >> 2) + half * 8;
                int en = ent[m];
                if (en < 0) continue;
                float v0 = c[mt][nt][half * 2 + 0] + bias[e * Ntot + col];
                float v1 = c[mt][nt][half * 2 + 1] + bias[e * Ntot + col + 1];
                if (MODE == 0) {
                    float ga = 0.5f * v0 * (1.0f + erff(v0 * 0.7071067811865476f));
                    float gb = 0.5f * v1 * (1.0f + erff(v1 * 0.7071067811865476f));
                    __half2 h2 = __floats2half2_rn(ga, gb);
                    *(uint32_t*)(outh + (size_t)en * Hn + col) = *(uint32_t*)&h2;
                } else {
                    float g = gw[m];
                    int t = en >> 1;
                    red2(outf + (size_t)t * Dn + col, v0 * g, v1 * g);
                }
            }
        }
    }

    if (MODE == 0) {
        __threadfence();           // make h stores visible device-wide
        __syncthreads();           // all threads' stores + fences done
        if (tid == 0) atomicAdd(done, 1);
    }
}

__global__ __launch_bounds__(256, 2) void fused_gemm(const __half* __restrict__ xh,
                                                     const __half* __restrict__ w1,
                                                     const float* __restrict__ b1,
                                                     __half* __restrict__ hh,
                                                     const __half* __restrict__ w2,
                                                     const float* __restrict__ b2,
                                                     float* __restrict__ y) {
    __shared__ int ent[128];
    __shared__ int rowIdx[128];
    __shared__ float gw[128];
    extern __shared__ char sdyn[];
    int bid = blockIdx.x;
    if (bid < G1BLKS) {
        int n = bid & 7, yt = (bid >> 3) & 63, e = bid >> 9;
        int cnt = g_counts[e];
        int row0 = yt * 128;
        if (row0 >= cnt) return;
        gemm_body<0>(n * 128, row0, cnt, e, xh, w1, b1, nullptr, hh,
                     sdyn, ent, rowIdx, gw, &g_done[e * 64 + yt]);
    } else {
        int b2i = bid - G1BLKS;
        int n = b2i & 3, yt = (b2i >> 2) & 63, e = b2i >> 8;
        int cnt = g_counts[e];
        int row0 = yt * 128;
        if (row0 >= cnt) return;
        gemm_body<1>(n * 128, row0, cnt, e, hh, w2, b2, y, nullptr,
                     sdyn, ent, rowIdx, gw, &g_done[e * 64 + yt]);
    }
}

// ---------------- launch ----------------------------------------------------
extern "C" void kernel_launch(void* const* d_in, const int* in_sizes, int n_in,
                              void* d_out, int out_size) {
    const float* x   = (const float*)d_in[0];
    const float* mus = (const float*)d_in[1];
    const float* ls  = (const float*)d_in[2];
    const float* W1  = (const float*)d_in[3];
    const float* b1  = (const float*)d_in[4];
    const float* W2  = (const float*)d_in[5];
    const float* b2  = (const float*)d_in[6];
    float* out = (float*)d_out;

    const int Ny  = Nn * Dn;
    const int Nlp = Nn * En;
    const int Nti = Nn * Kn;
    int has_lp = (out_size >= Ny + Nlp) ? 1 : 0;
    int has_ti = (out_size >= Ny + Nlp + Nti) ? 1 : 0;
    float* out_lp = out + Ny;
    float* out_ti = out + Ny + Nlp;

    cudaFuncSetAttribute(fused_gemm, cudaFuncAttributeMaxDynamicSharedMemorySize, NSTG * STG_BYTES);

    __half *w1, *w2, *hh, *xh;
    cudaGetSymbolAddress((void**)&w1, g_w1);
    cudaGetSymbolAddress((void**)&w2, g_w2);
    cudaGetSymbolAddress((void**)&hh, g_hh);
    cudaGetSymbolAddress((void**)&xh, g_xh);

    init_kernel<<<NW4 / 256 + Bn * En, 256>>>(W1, W2, w1, w2, ls, mus);

    gate_kernel<<<Nn / 16, 256>>>(x, xh, out, out_lp, out_ti, has_lp, has_ti);

    fused_gemm<<<G1BLKS + 2048, 256, NSTG * STG_BYTES>>>(xh, w1, b1, hh, w2, b2, out);

    (void)in_sizes; (void)n_in;
}